// round 1
// baseline (speedup 1.0000x reference)
#include <cuda_runtime.h>
#include <math.h>

// Problem constants (fixed by the dataset)
#define NB      8
#define LQ      300
#define CDIM    256
#define HEADS   8
#define NLVL    4
#define NPTS    8
#define DHEAD   32
#define LEN_IN  21760
#define NQ      (NB*LQ)         // 2400
#define MROWS   (NB*LEN_IN)     // 174080

// ---------------- scratch (device globals; no allocations allowed) ----------
__device__ float    g_value[(size_t)MROWS * CDIM];   // projected value, 178 MB
__device__ unsigned g_bits[NQ * 512];                // packed 128x128 bitmask per (n,q)
__device__ float    g_box[NQ * 4];                   // cx, cy, w, h
__device__ float    g_off[NQ * 512];                 // sampling offsets (h,l,p,2)
__device__ float    g_attn[NQ * 256];                // raw attention logits (h,l,p)
__device__ float    g_samp[NQ * 256];                // sampled output before W_out

// ---------------- kernel 1: mask -> packed bits + bounding box ---------------
__global__ __launch_bounds__(256) void mask_kernel(const float* __restrict__ masks) {
    int b = blockIdx.x;                     // n*LQ + q
    const float* m = masks + (size_t)b * 16384;
    __shared__ unsigned words[512];
    __shared__ unsigned colOr[4];
    __shared__ unsigned rowBits[4];
    int t = threadIdx.x;
    int lane = t & 31, warp = t >> 5;

    #pragma unroll 4
    for (int it = 0; it < 64; it++) {
        int idx = it * 256 + t;             // y = idx>>7, x = idx&127
        unsigned ball = __ballot_sync(0xffffffffu, m[idx] > 0.f);
        if (lane == 0) words[it * 8 + warp] = ball;   // word = y*4 + (x>>5)
    }
    __syncthreads();

    if (t < 4) {                            // column-any, 128 bits as 4 words
        unsigned o = 0;
        for (int y = 0; y < 128; y++) o |= words[y * 4 + t];
        colOr[t] = o;
    }
    if (t < 128) {                          // row-any -> 128 bits
        const unsigned* w = &words[t * 4];
        unsigned any = (w[0] | w[1] | w[2] | w[3]) != 0u;
        unsigned rb = __ballot_sync(0xffffffffu, any);
        if (lane == 0) rowBits[warp] = rb;
    }
    __syncthreads();

    if (t == 0) {
        int xmin = 128, xmax = -1, ymin = 128, ymax = -1;
        #pragma unroll
        for (int j = 0; j < 4; j++) {
            unsigned v = colOr[j];
            if (v) {
                int lo = __ffs(v) - 1 + 32 * j; if (lo < xmin) xmin = lo;
                int hi = 31 - __clz(v) + 32 * j; if (hi > xmax) xmax = hi;
            }
            unsigned r = rowBits[j];
            if (r) {
                int lo = __ffs(r) - 1 + 32 * j; if (lo < ymin) ymin = lo;
                int hi = 31 - __clz(r) + 32 * j; if (hi > ymax) ymax = hi;
            }
        }
        float4 box;
        if (xmax >= 0) {
            float x0 = xmin * (1.f/128.f), x1 = (xmax + 1) * (1.f/128.f);
            float y0 = ymin * (1.f/128.f), y1 = (ymax + 1) * (1.f/128.f);
            box = make_float4((x0 + x1) * 0.5f, (y0 + y1) * 0.5f, x1 - x0, y1 - y0);
        } else {
            box = make_float4(0.f, 0.f, 0.f, 0.f);
        }
        ((float4*)g_box)[b] = box;
    }
    unsigned* bo = g_bits + (size_t)b * 512;
    bo[t]       = words[t];
    bo[t + 256] = words[t + 256];
}

// ---------------- kernel 2/5: fp32 tiled SGEMM  C = A@B + bias --------------
// A: MxK row-major, B: KxN row-major. Optional per-row zeroing (padding mask).
template<int BM, int BN, int BK, int TM, int TN>
__global__ __launch_bounds__((BM/TM)*(BN/TN))
void sgemm_kernel(const float* __restrict__ A, const float* __restrict__ B,
                  const float* __restrict__ bias,
                  const unsigned char* __restrict__ rowzero,
                  float* __restrict__ Cmat, int M, int N, int K) {
    constexpr int THREADS = (BM/TM)*(BN/TN);
    __shared__ float As[BK][BM];
    __shared__ float Bs[BK][BN];
    const int block_row = blockIdx.y * BM;
    const int block_col = blockIdx.x * BN;
    const int tid  = threadIdx.x;
    const int tcol = tid % (BN/TN);
    const int trow = tid / (BN/TN);

    float acc[TM][TN];
    #pragma unroll
    for (int i = 0; i < TM; i++)
        #pragma unroll
        for (int j = 0; j < TN; j++) acc[i][j] = 0.f;

    constexpr int AV = (BM*BK)/(4*THREADS);
    constexpr int BV = (BK*BN)/(4*THREADS);

    for (int k0 = 0; k0 < K; k0 += BK) {
        #pragma unroll
        for (int i = 0; i < AV; i++) {
            int v = tid + i * THREADS;
            int r  = v / (BK/4);
            int c4 = (v % (BK/4)) * 4;
            int rg = block_row + r; if (rg > M - 1) rg = M - 1;   // tail clamp
            float4 a = *(const float4*)(A + (size_t)rg * K + k0 + c4);
            As[c4+0][r] = a.x; As[c4+1][r] = a.y; As[c4+2][r] = a.z; As[c4+3][r] = a.w;
        }
        #pragma unroll
        for (int i = 0; i < BV; i++) {
            int v = tid + i * THREADS;
            int r  = v / (BN/4);
            int c4 = (v % (BN/4)) * 4;
            *(float4*)(&Bs[r][c4]) = *(const float4*)(B + (size_t)(k0 + r) * N + block_col + c4);
        }
        __syncthreads();

        #pragma unroll
        for (int k = 0; k < BK; k++) {
            float ra[TM], rb[TN];
            #pragma unroll
            for (int i = 0; i < TM/2; i++) {
                ra[i]        = As[k][trow*(TM/2) + i];
                ra[i + TM/2] = As[k][BM/2 + trow*(TM/2) + i];
            }
            #pragma unroll
            for (int j = 0; j < TN/2; j++) {
                rb[j]        = Bs[k][tcol*(TN/2) + j];
                rb[j + TN/2] = Bs[k][BN/2 + tcol*(TN/2) + j];
            }
            #pragma unroll
            for (int i = 0; i < TM; i++)
                #pragma unroll
                for (int j = 0; j < TN; j++)
                    acc[i][j] += ra[i] * rb[j];
        }
        __syncthreads();
    }

    #pragma unroll
    for (int i = 0; i < TM; i++) {
        int rr = (i < TM/2) ? trow*(TM/2) + i : BM/2 + trow*(TM/2) + (i - TM/2);
        int r = block_row + rr;
        if (r >= M) continue;
        bool zero = (rowzero != nullptr) && rowzero[r];
        #pragma unroll
        for (int j = 0; j < TN; j++) {
            int cc = (j < TN/2) ? tcol*(TN/2) + j : BN/2 + tcol*(TN/2) + (j - TN/2);
            int c = block_col + cc;
            float v = acc[i][j] + bias[c];
            Cmat[(size_t)r * N + c] = zero ? 0.f : v;
        }
    }
}

// ---------------- kernel 3: offsets + attention logits projection ------------
// 16 queries per block; thread t computes cols t, 256+t of W_off and col t of W_attn.
__global__ __launch_bounds__(256) void proj_kernel(
        const float* __restrict__ query,
        const float* __restrict__ Woff, const float* __restrict__ boff,
        const float* __restrict__ Wattn, const float* __restrict__ battn) {
    int b0 = blockIdx.x * 16;
    __shared__ float q[16][256];
    int t = threadIdx.x;
    #pragma unroll
    for (int i = 0; i < 16; i++) q[i][t] = query[(size_t)(b0 + i) * 256 + t];
    __syncthreads();

    float a0[16], a1[16], a2[16];
    float bo0 = boff[t], bo1 = boff[256 + t], ba = battn[t];
    #pragma unroll
    for (int i = 0; i < 16; i++) { a0[i] = bo0; a1[i] = bo1; a2[i] = ba; }

    #pragma unroll 4
    for (int k = 0; k < 256; k++) {
        float w0 = Woff[k * 512 + t];
        float w1 = Woff[k * 512 + 256 + t];
        float w2 = Wattn[k * 256 + t];
        #pragma unroll
        for (int i = 0; i < 16; i++) {
            float qv = q[i][k];
            a0[i] += qv * w0;
            a1[i] += qv * w1;
            a2[i] += qv * w2;
        }
    }
    #pragma unroll
    for (int i = 0; i < 16; i++) {
        g_off[(size_t)(b0 + i) * 512 + t]       = a0[i];
        g_off[(size_t)(b0 + i) * 512 + 256 + t] = a1[i];
        g_attn[(size_t)(b0 + i) * 256 + t]      = a2[i];
    }
}

// ---------------- kernel 4: sampling + softmax + bilinear gather -------------
// 1 block per (n,q); warp h = head h. Phase A: lane = point (l*8+pt).
// Phase B: lane = channel d within the head.
__global__ __launch_bounds__(256) void sample_kernel() {
    int b = blockIdx.x;
    int n = b / LQ;
    int t = threadIdx.x, lane = t & 31, h = t >> 5;
    __shared__ int   s_idx[8][32][4];
    __shared__ float s_w[8][32][4];

    const int Wl_[4]    = {128, 64, 32, 16};
    const int start_[4] = {0, 16384, 20480, 21504};

    float4 box = ((const float4*)g_box)[b];

    // ---- phase A: per-point location, mask check, softmax, corner weights
    int p = lane, l = p >> 3;
    float ox = g_off[(size_t)b * 512 + (h * 32 + p) * 2 + 0];
    float oy = g_off[(size_t)b * 512 + (h * 32 + p) * 2 + 1];
    // loc = ctr + off/NPTS * wh * 0.5
    float locx = box.x + ox * (1.f / 16.f) * box.z;
    float locy = box.y + oy * (1.f / 16.f) * box.w;

    // point-in-mask on the 128x128 packed bitmask (trunc-toward-zero then clamp)
    int px = (int)(locx * 128.f); px = min(max(px, 0), 127);
    int py = (int)(locy * 128.f); py = min(max(py, 0), 127);
    unsigned wbits = g_bits[(size_t)b * 512 + py * 4 + (px >> 5)];
    float pin = ((wbits >> (px & 31)) & 1u) ? 1.f : 0.f;

    float logit = g_attn[(size_t)b * 256 + h * 32 + p] * pin;
    float mx = logit;
    #pragma unroll
    for (int o = 16; o; o >>= 1) mx = fmaxf(mx, __shfl_xor_sync(0xffffffffu, mx, o));
    float e = expf(logit - mx);
    float sm = e;
    #pragma unroll
    for (int o = 16; o; o >>= 1) sm += __shfl_xor_sync(0xffffffffu, sm, o);
    float aw = e / sm;

    int Wl = Wl_[l], Hl = Wl;
    float pxf = locx * (float)Wl - 0.5f;
    float pyf = locy * (float)Hl - 0.5f;
    float x0f = floorf(pxf), y0f = floorf(pyf);
    float wx = pxf - x0f, wy = pyf - y0f;
    int x0 = (int)x0f, y0 = (int)y0f;
    int base = n * LEN_IN + start_[l];

    #pragma unroll
    for (int k = 0; k < 4; k++) {
        int xi = x0 + (k & 1), yi = y0 + (k >> 1);
        float cw = ((k & 1) ? wx : 1.f - wx) * ((k >> 1) ? wy : 1.f - wy);
        bool valid = (xi >= 0) && (xi < Wl) && (yi >= 0) && (yi < Hl);
        int xc = min(max(xi, 0), Wl - 1);
        int yc = min(max(yi, 0), Hl - 1);
        s_idx[h][p][k] = base + yc * Wl + xc;
        s_w[h][p][k]   = valid ? cw * aw : 0.f;
    }
    __syncwarp();

    // ---- phase B: lane = channel d; coalesced 128B gathers from g_value
    int d = lane;
    const float* vcol = g_value + h * 32 + d;
    float acc = 0.f;
    #pragma unroll 4
    for (int pp = 0; pp < 32; pp++) {
        #pragma unroll
        for (int k = 0; k < 4; k++) {
            float wgt = s_w[h][pp][k];                 // warp-uniform branch
            if (wgt != 0.f)
                acc += wgt * vcol[(size_t)s_idx[h][pp][k] * 256];
        }
    }
    g_samp[(size_t)b * 256 + h * 32 + d] = acc;
}

// ---------------- launch --------------------------------------------------
extern "C" void kernel_launch(void* const* d_in, const int* in_sizes, int n_in,
                              void* d_out, int out_size) {
    const float* query = (const float*)d_in[0];
    // d_in[1] reference_bboxs: unused by reference
    const float* masks = (const float*)d_in[2];
    // d_in[3] mask_threshold: reference hard-codes > 0
    const float* flat  = (const float*)d_in[4];
    // d_in[5], d_in[6]: spatial shapes / level starts (compile-time constants)
    const unsigned char* pad = (const unsigned char*)d_in[7];
    const float* Woff  = (const float*)d_in[8];
    const float* boff  = (const float*)d_in[9];
    const float* Wattn = (const float*)d_in[10];
    const float* battn = (const float*)d_in[11];
    const float* Wval  = (const float*)d_in[12];
    const float* bval  = (const float*)d_in[13];
    const float* Wout  = (const float*)d_in[14];
    const float* bout  = (const float*)d_in[15];
    float* out = (float*)d_out;

    float *valp = nullptr, *sampp = nullptr;
    cudaGetSymbolAddress((void**)&valp, g_value);
    cudaGetSymbolAddress((void**)&sampp, g_samp);

    // 1) masks -> packed bits + bboxes
    mask_kernel<<<NQ, 256>>>(masks);

    // 2) value = input_flatten @ W_val + b_val (zero padded rows)
    sgemm_kernel<128,128,16,8,8><<<dim3(CDIM/128, MROWS/128), 256>>>(
        flat, Wval, bval, pad, valp, MROWS, CDIM, CDIM);

    // 3) offsets + attention logits
    proj_kernel<<<NQ/16, 256>>>(query, Woff, boff, Wattn, battn);

    // 4) softmax + bilinear sampling
    sample_kernel<<<NQ, 256>>>();

    // 5) out = sampled @ W_out + b_out
    sgemm_kernel<64,64,16,4,4><<<dim3(CDIM/64, (NQ + 63)/64), 256>>>(
        sampp, Wout, bout, nullptr, out, NQ, CDIM, CDIM);
}

// round 3
// speedup vs baseline: 1.2695x; 1.2695x over previous
#include <cuda_runtime.h>
#include <cuda_bf16.h>
#include <math.h>
#include <stdint.h>

// Problem constants (fixed by the dataset)
#define NB      8
#define LQ      300
#define CDIM    256
#define HEADS   8
#define NLVL    4
#define NPTS    8
#define DHEAD   32
#define LEN_IN  21760
#define NQ      (NB*LQ)         // 2400
#define MROWS   (NB*LEN_IN)     // 174080

// ---------------- scratch (device globals; no allocations allowed) ----------
__device__ float    g_value[(size_t)MROWS * CDIM];   // projected value, 178 MB
__device__ unsigned g_bits[NQ * 512];                // packed 128x128 bitmask per (n,q)
__device__ float    g_box[NQ * 4];                   // cx, cy, w, h
__device__ float    g_off[NQ * 512];                 // sampling offsets (h,l,p,2)
__device__ float    g_attn[NQ * 256];                // raw attention logits (h,l,p)
__device__ float    g_samp[NQ * 256];                // sampled output before W_out
// W_val^T pre-shuffled into m16n8k16 B-fragment layout, hi/lo bf16 splits.
// Index: ((ntile*16 + kstep)*32 + lane) -> uint2 {b0, b1}
__device__ uint2    g_BfHi[32 * 16 * 32];
__device__ uint2    g_BfLo[32 * 16 * 32];

// ---------------- HMMA helpers ----------------------------------------------
__device__ __forceinline__ void mma16816(float* c, const uint32_t* a, const uint2 b) {
    asm volatile(
        "mma.sync.aligned.m16n8k16.row.col.f32.bf16.bf16.f32 "
        "{%0,%1,%2,%3}, {%4,%5,%6,%7}, {%8,%9}, {%0,%1,%2,%3};\n"
        : "+f"(c[0]), "+f"(c[1]), "+f"(c[2]), "+f"(c[3])
        : "r"(a[0]), "r"(a[1]), "r"(a[2]), "r"(a[3]), "r"(b.x), "r"(b.y));
}
__device__ __forceinline__ void cvt_hilo(float2 v, uint32_t& hi, uint32_t& lo) {
    __nv_bfloat162 h = __floats2bfloat162_rn(v.x, v.y);
    float2 f = __bfloat1622float2(h);
    __nv_bfloat162 l = __floats2bfloat162_rn(v.x - f.x, v.y - f.y);
    hi = *(uint32_t*)&h;
    lo = *(uint32_t*)&l;
}

// ================= kernel 0: W_val^T -> bf16 hi/lo fragment layout ==========
__global__ __launch_bounds__(256) void prep_B(const float* __restrict__ W) {
    int idx = blockIdx.x * 256 + threadIdx.x;     // 16384 threads
    int lane  = idx & 31;
    int ks    = (idx >> 5) & 15;
    int ntile = idx >> 9;                         // 0..31
    int n  = ntile * 8 + (lane >> 2);             // output column of W_val
    int kb = ks * 16 + (lane & 3) * 2;            // k base
    // B[n][k] = W[k*256 + n]
    float x0 = W[(kb + 0) * 256 + n];
    float x1 = W[(kb + 1) * 256 + n];
    float x2 = W[(kb + 8) * 256 + n];
    float x3 = W[(kb + 9) * 256 + n];
    uint32_t h0, l0, h1, l1;
    cvt_hilo(make_float2(x0, x1), h0, l0);
    cvt_hilo(make_float2(x2, x3), h1, l1);
    g_BfHi[idx] = make_uint2(h0, h1);
    g_BfLo[idx] = make_uint2(l0, l1);
}

// ================= kernel: HMMA split-bf16 value GEMM =======================
// C tile 128x128 per CTA; 8 warps in 4(M)x2(N); warp tile 32x64.
// Three bf16 products (AhBh + AhBl + AlBh) into fp32 accumulators.
__global__ __launch_bounds__(256) void value_gemm(
        const float* __restrict__ A, const unsigned char* __restrict__ pad,
        const float* __restrict__ bias) {
    const int tid = threadIdx.x, lane = tid & 31, wid = tid >> 5;
    const int g = lane >> 2, t = lane & 3;
    const int tileRow = blockIdx.x * 128;
    const int rowBase = tileRow + (wid & 3) * 32 + g;      // row of a0 for frag i=0
    const int colBase = blockIdx.y * 128 + (wid >> 2) * 64;
    const int ntb = colBase >> 3;                           // first B ntile for this warp

    float2 bias2[8];
    #pragma unroll
    for (int j = 0; j < 8; j++)
        bias2[j] = *(const float2*)(bias + colBase + j * 8 + t * 2);

    float acc[2][8][4];
    #pragma unroll
    for (int i = 0; i < 2; i++)
        #pragma unroll
        for (int j = 0; j < 8; j++)
            #pragma unroll
            for (int q = 0; q < 4; q++) acc[i][j][q] = 0.f;

    // raw A double buffer: [buf][frag i][reg q]
    float2 araw[2][2][4];
    #define LOAD_A(ks, buf) { \
        _Pragma("unroll") \
        for (int i = 0; i < 2; i++) { \
            const float* bp = A + (size_t)(rowBase + i * 16) * 256 + (ks) * 16 + t * 2; \
            araw[buf][i][0] = *(const float2*)(bp); \
            araw[buf][i][1] = *(const float2*)(bp + 8 * 256); \
            araw[buf][i][2] = *(const float2*)(bp + 8); \
            araw[buf][i][3] = *(const float2*)(bp + 8 * 256 + 8); \
        } }

    LOAD_A(0, 0);
    #pragma unroll
    for (int ks = 0; ks < 16; ks++) {
        const int cur = ks & 1;
        if (ks < 15) LOAD_A(ks + 1, cur ^ 1);

        // B fragments for this k-step (coalesced LDG.64, L1/L2 resident)
        uint2 bhi[8], blo[8];
        #pragma unroll
        for (int j = 0; j < 8; j++) {
            int bidx = ((ntb + j) * 16 + ks) * 32 + lane;
            bhi[j] = g_BfHi[bidx];
            blo[j] = g_BfLo[bidx];
        }
        // A fragments: fp32 -> bf16 hi/lo in regs
        uint32_t ahi[2][4], alo[2][4];
        #pragma unroll
        for (int i = 0; i < 2; i++)
            #pragma unroll
            for (int q = 0; q < 4; q++)
                cvt_hilo(araw[cur][i][q], ahi[i][q], alo[i][q]);

        #pragma unroll
        for (int i = 0; i < 2; i++)
            #pragma unroll
            for (int j = 0; j < 8; j++) {
                mma16816(acc[i][j], ahi[i], bhi[j]);
                mma16816(acc[i][j], ahi[i], blo[j]);
                mma16816(acc[i][j], alo[i], bhi[j]);
            }
    }
    #undef LOAD_A

    // ---- epilogue: bias add, padding zero, float2 stores
    #pragma unroll
    for (int i = 0; i < 2; i++) {
        int ra = rowBase + i * 16;
        int rb = ra + 8;
        bool pa = pad[ra] != 0, pb = pad[rb] != 0;
        #pragma unroll
        for (int j = 0; j < 8; j++) {
            int c0 = colBase + j * 8 + t * 2;
            float2 oa, ob;
            oa.x = pa ? 0.f : acc[i][j][0] + bias2[j].x;
            oa.y = pa ? 0.f : acc[i][j][1] + bias2[j].y;
            ob.x = pb ? 0.f : acc[i][j][2] + bias2[j].x;
            ob.y = pb ? 0.f : acc[i][j][3] + bias2[j].y;
            *(float2*)(g_value + (size_t)ra * 256 + c0) = oa;
            *(float2*)(g_value + (size_t)rb * 256 + c0) = ob;
        }
    }
}

// ---------------- kernel 1: mask -> packed bits + bounding box ---------------
__global__ __launch_bounds__(256) void mask_kernel(const float* __restrict__ masks) {
    int b = blockIdx.x;
    const float* m = masks + (size_t)b * 16384;
    __shared__ unsigned words[512];
    __shared__ unsigned colOr[4];
    __shared__ unsigned rowBits[4];
    int t = threadIdx.x;
    int lane = t & 31, warp = t >> 5;

    #pragma unroll 4
    for (int it = 0; it < 64; it++) {
        int idx = it * 256 + t;
        unsigned ball = __ballot_sync(0xffffffffu, m[idx] > 0.f);
        if (lane == 0) words[it * 8 + warp] = ball;
    }
    __syncthreads();

    if (t < 4) {
        unsigned o = 0;
        for (int y = 0; y < 128; y++) o |= words[y * 4 + t];
        colOr[t] = o;
    }
    if (t < 128) {
        const unsigned* w = &words[t * 4];
        unsigned any = (w[0] | w[1] | w[2] | w[3]) != 0u;
        unsigned rb = __ballot_sync(0xffffffffu, any);
        if (lane == 0) rowBits[warp] = rb;
    }
    __syncthreads();

    if (t == 0) {
        int xmin = 128, xmax = -1, ymin = 128, ymax = -1;
        #pragma unroll
        for (int j = 0; j < 4; j++) {
            unsigned v = colOr[j];
            if (v) {
                int lo = __ffs(v) - 1 + 32 * j; if (lo < xmin) xmin = lo;
                int hi = 31 - __clz(v) + 32 * j; if (hi > xmax) xmax = hi;
            }
            unsigned r = rowBits[j];
            if (r) {
                int lo = __ffs(r) - 1 + 32 * j; if (lo < ymin) ymin = lo;
                int hi = 31 - __clz(r) + 32 * j; if (hi > ymax) ymax = hi;
            }
        }
        float4 box;
        if (xmax >= 0) {
            float x0 = xmin * (1.f/128.f), x1 = (xmax + 1) * (1.f/128.f);
            float y0 = ymin * (1.f/128.f), y1 = (ymax + 1) * (1.f/128.f);
            box = make_float4((x0 + x1) * 0.5f, (y0 + y1) * 0.5f, x1 - x0, y1 - y0);
        } else {
            box = make_float4(0.f, 0.f, 0.f, 0.f);
        }
        ((float4*)g_box)[b] = box;
    }
    unsigned* bo = g_bits + (size_t)b * 512;
    bo[t]       = words[t];
    bo[t + 256] = words[t + 256];
}

// ---------------- fp32 tiled SGEMM (small out-projection only) --------------
template<int BM, int BN, int BK, int TM, int TN>
__global__ __launch_bounds__((BM/TM)*(BN/TN))
void sgemm_kernel(const float* __restrict__ A, const float* __restrict__ B,
                  const float* __restrict__ bias,
                  float* __restrict__ Cmat, int M, int N, int K) {
    constexpr int THREADS = (BM/TM)*(BN/TN);
    __shared__ float As[BK][BM];
    __shared__ float Bs[BK][BN];
    const int block_row = blockIdx.y * BM;
    const int block_col = blockIdx.x * BN;
    const int tid  = threadIdx.x;
    const int tcol = tid % (BN/TN);
    const int trow = tid / (BN/TN);

    float acc[TM][TN];
    #pragma unroll
    for (int i = 0; i < TM; i++)
        #pragma unroll
        for (int j = 0; j < TN; j++) acc[i][j] = 0.f;

    constexpr int AV = (BM*BK)/(4*THREADS);
    constexpr int BV = (BK*BN)/(4*THREADS);

    for (int k0 = 0; k0 < K; k0 += BK) {
        #pragma unroll
        for (int i = 0; i < AV; i++) {
            int v = tid + i * THREADS;
            int r  = v / (BK/4);
            int c4 = (v % (BK/4)) * 4;
            int rg = block_row + r; if (rg > M - 1) rg = M - 1;
            float4 a = *(const float4*)(A + (size_t)rg * K + k0 + c4);
            As[c4+0][r] = a.x; As[c4+1][r] = a.y; As[c4+2][r] = a.z; As[c4+3][r] = a.w;
        }
        #pragma unroll
        for (int i = 0; i < BV; i++) {
            int v = tid + i * THREADS;
            int r  = v / (BN/4);
            int c4 = (v % (BN/4)) * 4;
            *(float4*)(&Bs[r][c4]) = *(const float4*)(B + (size_t)(k0 + r) * N + block_col + c4);
        }
        __syncthreads();

        #pragma unroll
        for (int k = 0; k < BK; k++) {
            float ra[TM], rb[TN];
            #pragma unroll
            for (int i = 0; i < TM/2; i++) {
                ra[i]        = As[k][trow*(TM/2) + i];
                ra[i + TM/2] = As[k][BM/2 + trow*(TM/2) + i];
            }
            #pragma unroll
            for (int j = 0; j < TN/2; j++) {
                rb[j]        = Bs[k][tcol*(TN/2) + j];
                rb[j + TN/2] = Bs[k][BN/2 + tcol*(TN/2) + j];
            }
            #pragma unroll
            for (int i = 0; i < TM; i++)
                #pragma unroll
                for (int j = 0; j < TN; j++)
                    acc[i][j] += ra[i] * rb[j];
        }
        __syncthreads();
    }

    #pragma unroll
    for (int i = 0; i < TM; i++) {
        int rr = (i < TM/2) ? trow*(TM/2) + i : BM/2 + trow*(TM/2) + (i - TM/2);
        int r = block_row + rr;
        if (r >= M) continue;
        #pragma unroll
        for (int j = 0; j < TN; j++) {
            int cc = (j < TN/2) ? tcol*(TN/2) + j : BN/2 + tcol*(TN/2) + (j - TN/2);
            int c = block_col + cc;
            Cmat[(size_t)r * N + c] = acc[i][j] + bias[c];
        }
    }
}

// ---------------- kernel 3: offsets + attention logits projection ------------
__global__ __launch_bounds__(256) void proj_kernel(
        const float* __restrict__ query,
        const float* __restrict__ Woff, const float* __restrict__ boff,
        const float* __restrict__ Wattn, const float* __restrict__ battn) {
    int b0 = blockIdx.x * 16;
    __shared__ float q[16][256];
    int t = threadIdx.x;
    #pragma unroll
    for (int i = 0; i < 16; i++) q[i][t] = query[(size_t)(b0 + i) * 256 + t];
    __syncthreads();

    float a0[16], a1[16], a2[16];
    float bo0 = boff[t], bo1 = boff[256 + t], ba = battn[t];
    #pragma unroll
    for (int i = 0; i < 16; i++) { a0[i] = bo0; a1[i] = bo1; a2[i] = ba; }

    #pragma unroll 4
    for (int k = 0; k < 256; k++) {
        float w0 = Woff[k * 512 + t];
        float w1 = Woff[k * 512 + 256 + t];
        float w2 = Wattn[k * 256 + t];
        #pragma unroll
        for (int i = 0; i < 16; i++) {
            float qv = q[i][k];
            a0[i] += qv * w0;
            a1[i] += qv * w1;
            a2[i] += qv * w2;
        }
    }
    #pragma unroll
    for (int i = 0; i < 16; i++) {
        g_off[(size_t)(b0 + i) * 512 + t]       = a0[i];
        g_off[(size_t)(b0 + i) * 512 + 256 + t] = a1[i];
        g_attn[(size_t)(b0 + i) * 256 + t]      = a2[i];
    }
}

// ---------------- kernel 4: sampling + softmax + bilinear gather -------------
__global__ __launch_bounds__(256) void sample_kernel() {
    int b = blockIdx.x;
    int n = b / LQ;
    int t = threadIdx.x, lane = t & 31, h = t >> 5;
    __shared__ int   s_idx[8][32][4];
    __shared__ float s_w[8][32][4];

    const int Wl_[4]    = {128, 64, 32, 16};
    const int start_[4] = {0, 16384, 20480, 21504};

    float4 box = ((const float4*)g_box)[b];

    int p = lane, l = p >> 3;
    float ox = g_off[(size_t)b * 512 + (h * 32 + p) * 2 + 0];
    float oy = g_off[(size_t)b * 512 + (h * 32 + p) * 2 + 1];
    float locx = box.x + ox * (1.f / 16.f) * box.z;
    float locy = box.y + oy * (1.f / 16.f) * box.w;

    int px = (int)(locx * 128.f); px = min(max(px, 0), 127);
    int py = (int)(locy * 128.f); py = min(max(py, 0), 127);
    unsigned wbits = g_bits[(size_t)b * 512 + py * 4 + (px >> 5)];
    float pin = ((wbits >> (px & 31)) & 1u) ? 1.f : 0.f;

    float logit = g_attn[(size_t)b * 256 + h * 32 + p] * pin;
    float mx = logit;
    #pragma unroll
    for (int o = 16; o; o >>= 1) mx = fmaxf(mx, __shfl_xor_sync(0xffffffffu, mx, o));
    float e = expf(logit - mx);
    float sm = e;
    #pragma unroll
    for (int o = 16; o; o >>= 1) sm += __shfl_xor_sync(0xffffffffu, sm, o);
    float aw = e / sm;

    int Wl = Wl_[l], Hl = Wl;
    float pxf = locx * (float)Wl - 0.5f;
    float pyf = locy * (float)Hl - 0.5f;
    float x0f = floorf(pxf), y0f = floorf(pyf);
    float wx = pxf - x0f, wy = pyf - y0f;
    int x0 = (int)x0f, y0 = (int)y0f;
    int base = n * LEN_IN + start_[l];

    #pragma unroll
    for (int k = 0; k < 4; k++) {
        int xi = x0 + (k & 1), yi = y0 + (k >> 1);
        float cw = ((k & 1) ? wx : 1.f - wx) * ((k >> 1) ? wy : 1.f - wy);
        bool valid = (xi >= 0) && (xi < Wl) && (yi >= 0) && (yi < Hl);
        int xc = min(max(xi, 0), Wl - 1);
        int yc = min(max(yi, 0), Hl - 1);
        s_idx[h][p][k] = base + yc * Wl + xc;
        s_w[h][p][k]   = valid ? cw * aw : 0.f;
    }
    __syncwarp();

    int d = lane;
    const float* vcol = g_value + h * 32 + d;
    float acc = 0.f;
    #pragma unroll 4
    for (int pp = 0; pp < 32; pp++) {
        #pragma unroll
        for (int k = 0; k < 4; k++) {
            float wgt = s_w[h][pp][k];
            if (wgt != 0.f)
                acc += wgt * vcol[(size_t)s_idx[h][pp][k] * 256];
        }
    }
    g_samp[(size_t)b * 256 + h * 32 + d] = acc;
}

// ---------------- launch --------------------------------------------------
extern "C" void kernel_launch(void* const* d_in, const int* in_sizes, int n_in,
                              void* d_out, int out_size) {
    const float* query = (const float*)d_in[0];
    const float* masks = (const float*)d_in[2];
    const float* flat  = (const float*)d_in[4];
    const unsigned char* pad = (const unsigned char*)d_in[7];
    const float* Woff  = (const float*)d_in[8];
    const float* boff  = (const float*)d_in[9];
    const float* Wattn = (const float*)d_in[10];
    const float* battn = (const float*)d_in[11];
    const float* Wval  = (const float*)d_in[12];
    const float* bval  = (const float*)d_in[13];
    const float* Wout  = (const float*)d_in[14];
    const float* bout  = (const float*)d_in[15];
    float* out = (float*)d_out;

    float* sampp = nullptr;
    cudaGetSymbolAddress((void**)&sampp, g_samp);

    // 1) masks -> packed bits + bboxes
    mask_kernel<<<NQ, 256>>>(masks);

    // 2) W_val^T -> bf16 hi/lo fragment layout, then HMMA value GEMM
    prep_B<<<64, 256>>>(Wval);
    value_gemm<<<dim3(MROWS/128, 2), 256>>>(flat, pad, bval);

    // 3) offsets + attention logits
    proj_kernel<<<NQ/16, 256>>>(query, Woff, boff, Wattn, battn);

    // 4) softmax + bilinear sampling
    sample_kernel<<<NQ, 256>>>();

    // 5) out = sampled @ W_out + b_out
    sgemm_kernel<64,64,16,4,4><<<dim3(CDIM/64, (NQ + 63)/64), 256>>>(
        sampp, Wout, bout, out, NQ, CDIM, CDIM);
}

// round 4
// speedup vs baseline: 1.8252x; 1.4377x over previous
#include <cuda_runtime.h>
#include <cuda_bf16.h>
#include <cuda_fp16.h>
#include <math.h>
#include <stdint.h>

// Problem constants (fixed by the dataset)
#define NB      8
#define LQ      300
#define CDIM    256
#define HEADS   8
#define NLVL    4
#define NPTS    8
#define DHEAD   32
#define LEN_IN  21760
#define NQ      (NB*LQ)         // 2400
#define MROWS   (NB*LEN_IN)     // 174080

// ---------------- scratch (device globals; no allocations allowed) ----------
__device__ float    g_value[(size_t)MROWS * CDIM];   // projected value, 178 MB
__device__ unsigned g_bits[NQ * 512];                // packed 128x128 bitmask per (n,q)
__device__ float    g_box[NQ * 4];                   // cx, cy, w, h
__device__ float    g_off[NQ * 512];                 // sampling offsets (h,l,p,2)
__device__ float    g_attn[NQ * 256];                // raw attention logits (h,l,p)
__device__ float    g_samp[NQ * 256];                // sampled output before W_out
// W_val^T in m16n8k16 B-fragment layout, fp16 hi/lo splits.
// Index: ((ntile*16 + kstep)*32 + lane) -> uint2 {b0, b1}
__device__ uint2    g_BfHi[32 * 16 * 32];
__device__ uint2    g_BfLo[32 * 16 * 32];
// [Woff | Wattn] (N=768) in B-fragment layout, fp16 hi/lo splits.
__device__ uint2    g_PfHi[96 * 16 * 32];
__device__ uint2    g_PfLo[96 * 16 * 32];

// ---------------- HMMA helpers ----------------------------------------------
__device__ __forceinline__ void mma16816(float* c, const uint32_t* a, const uint2 b) {
    asm volatile(
        "mma.sync.aligned.m16n8k16.row.col.f32.f16.f16.f32 "
        "{%0,%1,%2,%3}, {%4,%5,%6,%7}, {%8,%9}, {%0,%1,%2,%3};\n"
        : "+f"(c[0]), "+f"(c[1]), "+f"(c[2]), "+f"(c[3])
        : "r"(a[0]), "r"(a[1]), "r"(a[2]), "r"(a[3]), "r"(b.x), "r"(b.y));
}
__device__ __forceinline__ uint32_t cvt_h(float2 v) {
    __half2 h = __float22half2_rn(v);
    return *(uint32_t*)&h;
}
__device__ __forceinline__ void cvt_hilo(float2 v, uint32_t& hi, uint32_t& lo) {
    __half2 h = __float22half2_rn(v);
    float2 f = __half22float2(h);
    __half2 l = __float22half2_rn(make_float2(v.x - f.x, v.y - f.y));
    hi = *(uint32_t*)&h;
    lo = *(uint32_t*)&l;
}

// ================= prep: W_val^T -> fp16 hi/lo fragment layout ==============
__global__ __launch_bounds__(256) void prep_Bval(const float* __restrict__ W) {
    int idx = blockIdx.x * 256 + threadIdx.x;     // 16384 threads
    int lane  = idx & 31;
    int ks    = (idx >> 5) & 15;
    int ntile = idx >> 9;                         // 0..31
    int n  = ntile * 8 + (lane >> 2);             // output column of W_val
    int kb = ks * 16 + (lane & 3) * 2;            // k base
    float x0 = W[(kb + 0) * 256 + n];
    float x1 = W[(kb + 1) * 256 + n];
    float x2 = W[(kb + 8) * 256 + n];
    float x3 = W[(kb + 9) * 256 + n];
    uint32_t h0, l0, h1, l1;
    cvt_hilo(make_float2(x0, x1), h0, l0);
    cvt_hilo(make_float2(x2, x3), h1, l1);
    g_BfHi[idx] = make_uint2(h0, h1);
    g_BfLo[idx] = make_uint2(l0, l1);
}

// ================= prep: [Woff | Wattn]^T -> fp16 hi/lo fragments ===========
__global__ __launch_bounds__(256) void prep_Bproj(
        const float* __restrict__ Woff, const float* __restrict__ Wattn) {
    int idx = blockIdx.x * 256 + threadIdx.x;     // 49152 threads
    int lane  = idx & 31;
    int ks    = (idx >> 5) & 15;
    int ntile = idx >> 9;                         // 0..95
    int n  = ntile * 8 + (lane >> 2);             // 0..767
    int kb = ks * 16 + (lane & 3) * 2;
    float x[4];
    #pragma unroll
    for (int q = 0; q < 4; q++) {
        int k = kb + (q >> 1) * 8 + (q & 1);
        x[q] = (n < 512) ? Woff[k * 512 + n] : Wattn[k * 256 + (n - 512)];
    }
    uint32_t h0, l0, h1, l1;
    cvt_hilo(make_float2(x[0], x[1]), h0, l0);
    cvt_hilo(make_float2(x[2], x[3]), h1, l1);
    g_PfHi[idx] = make_uint2(h0, h1);
    g_PfLo[idx] = make_uint2(l0, l1);
}

// ================= kernel: HMMA 2-term fp16 value GEMM ======================
// C tile 128x128 per CTA; 8 warps in 4(M)x2(N); warp tile 32x64.
// value = Ah*Bh + Ah*Bl (B split exact-ish; dropped Al*B ~ 2e-4 relative).
__global__ __launch_bounds__(256) void value_gemm(
        const float* __restrict__ A, const unsigned char* __restrict__ pad,
        const float* __restrict__ bias) {
    const int tid = threadIdx.x, lane = tid & 31, wid = tid >> 5;
    const int g = lane >> 2, t = lane & 3;
    const int rowBase = blockIdx.x * 128 + (wid & 3) * 32 + g;
    const int colBase = blockIdx.y * 128 + (wid >> 2) * 64;
    const int ntb = colBase >> 3;

    float2 bias2[8];
    #pragma unroll
    for (int j = 0; j < 8; j++)
        bias2[j] = *(const float2*)(bias + colBase + j * 8 + t * 2);

    float acc[2][8][4];
    #pragma unroll
    for (int i = 0; i < 2; i++)
        #pragma unroll
        for (int j = 0; j < 8; j++)
            #pragma unroll
            for (int q = 0; q < 4; q++) acc[i][j][q] = 0.f;

    float2 araw[2][2][4];
    #define LOAD_A(ks, buf) { \
        _Pragma("unroll") \
        for (int i = 0; i < 2; i++) { \
            const float* bp = A + (size_t)(rowBase + i * 16) * 256 + (ks) * 16 + t * 2; \
            araw[buf][i][0] = *(const float2*)(bp); \
            araw[buf][i][1] = *(const float2*)(bp + 8 * 256); \
            araw[buf][i][2] = *(const float2*)(bp + 8); \
            araw[buf][i][3] = *(const float2*)(bp + 8 * 256 + 8); \
        } }

    LOAD_A(0, 0);
    #pragma unroll
    for (int ks = 0; ks < 16; ks++) {
        const int cur = ks & 1;
        if (ks < 15) LOAD_A(ks + 1, cur ^ 1);

        uint2 bhi[8], blo[8];
        #pragma unroll
        for (int j = 0; j < 8; j++) {
            int bidx = ((ntb + j) * 16 + ks) * 32 + lane;
            bhi[j] = g_BfHi[bidx];
            blo[j] = g_BfLo[bidx];
        }
        uint32_t ah[2][4];
        #pragma unroll
        for (int i = 0; i < 2; i++)
            #pragma unroll
            for (int q = 0; q < 4; q++)
                ah[i][q] = cvt_h(araw[cur][i][q]);

        #pragma unroll
        for (int i = 0; i < 2; i++)
            #pragma unroll
            for (int j = 0; j < 8; j++) {
                mma16816(acc[i][j], ah[i], bhi[j]);
                mma16816(acc[i][j], ah[i], blo[j]);
            }
    }
    #undef LOAD_A

    #pragma unroll
    for (int i = 0; i < 2; i++) {
        int ra = rowBase + i * 16;
        int rb = ra + 8;
        bool pa = pad[ra] != 0, pb = pad[rb] != 0;
        #pragma unroll
        for (int j = 0; j < 8; j++) {
            int c0 = colBase + j * 8 + t * 2;
            float2 oa, ob;
            oa.x = pa ? 0.f : acc[i][j][0] + bias2[j].x;
            oa.y = pa ? 0.f : acc[i][j][1] + bias2[j].y;
            ob.x = pb ? 0.f : acc[i][j][2] + bias2[j].x;
            ob.y = pb ? 0.f : acc[i][j][3] + bias2[j].y;
            *(float2*)(g_value + (size_t)ra * 256 + c0) = oa;
            *(float2*)(g_value + (size_t)rb * 256 + c0) = ob;
        }
    }
}

// ================= kernel: HMMA 3-term fp16 proj GEMM =======================
// [offsets | logits] = query @ [Woff | Wattn] + bias. M=2400, N=768, K=256.
// Full-precision split (AhBh + AhBl + AlBh): offsets feed discrete ops.
__global__ __launch_bounds__(256) void proj_gemm(
        const float* __restrict__ Q,
        const float* __restrict__ boff, const float* __restrict__ battn) {
    const int tid = threadIdx.x, lane = tid & 31, wid = tid >> 5;
    const int g = lane >> 2, t = lane & 3;
    const int rowBase = blockIdx.x * 128 + (wid & 3) * 32 + g;
    const int colBase = blockIdx.y * 128 + (wid >> 2) * 64;
    const int ntb = colBase >> 3;

    float2 bias2[8];
    #pragma unroll
    for (int j = 0; j < 8; j++) {
        int c = colBase + j * 8 + t * 2;
        bias2[j] = (c < 512) ? *(const float2*)(boff + c)
                             : *(const float2*)(battn + (c - 512));
    }

    float acc[2][8][4];
    #pragma unroll
    for (int i = 0; i < 2; i++)
        #pragma unroll
        for (int j = 0; j < 8; j++)
            #pragma unroll
            for (int q = 0; q < 4; q++) acc[i][j][q] = 0.f;

    float2 araw[2][2][4];
    #define LOAD_AQ(ks, buf) { \
        _Pragma("unroll") \
        for (int i = 0; i < 2; i++) { \
            int r0 = min(rowBase + i * 16, NQ - 1); \
            int r1 = min(rowBase + i * 16 + 8, NQ - 1); \
            const float* b0 = Q + (size_t)r0 * 256 + (ks) * 16 + t * 2; \
            const float* b1 = Q + (size_t)r1 * 256 + (ks) * 16 + t * 2; \
            araw[buf][i][0] = *(const float2*)(b0); \
            araw[buf][i][1] = *(const float2*)(b1); \
            araw[buf][i][2] = *(const float2*)(b0 + 8); \
            araw[buf][i][3] = *(const float2*)(b1 + 8); \
        } }

    LOAD_AQ(0, 0);
    #pragma unroll
    for (int ks = 0; ks < 16; ks++) {
        const int cur = ks & 1;
        if (ks < 15) LOAD_AQ(ks + 1, cur ^ 1);

        uint2 bhi[8], blo[8];
        #pragma unroll
        for (int j = 0; j < 8; j++) {
            int bidx = ((ntb + j) * 16 + ks) * 32 + lane;
            bhi[j] = g_PfHi[bidx];
            blo[j] = g_PfLo[bidx];
        }
        uint32_t ahi[2][4], alo[2][4];
        #pragma unroll
        for (int i = 0; i < 2; i++)
            #pragma unroll
            for (int q = 0; q < 4; q++)
                cvt_hilo(araw[cur][i][q], ahi[i][q], alo[i][q]);

        #pragma unroll
        for (int i = 0; i < 2; i++)
            #pragma unroll
            for (int j = 0; j < 8; j++) {
                mma16816(acc[i][j], ahi[i], bhi[j]);
                mma16816(acc[i][j], ahi[i], blo[j]);
                mma16816(acc[i][j], alo[i], bhi[j]);
            }
    }
    #undef LOAD_AQ

    #pragma unroll
    for (int i = 0; i < 2; i++) {
        #pragma unroll
        for (int q2 = 0; q2 < 2; q2++) {                 // q2=0 -> row+0, q2=1 -> row+8
            int r = rowBase + i * 16 + q2 * 8;
            if (r >= NQ) continue;
            #pragma unroll
            for (int j = 0; j < 8; j++) {
                int c0 = colBase + j * 8 + t * 2;
                float2 o;
                o.x = acc[i][j][q2 * 2 + 0] + bias2[j].x;
                o.y = acc[i][j][q2 * 2 + 1] + bias2[j].y;
                if (c0 < 512) *(float2*)(g_off  + (size_t)r * 512 + c0)         = o;
                else          *(float2*)(g_attn + (size_t)r * 256 + (c0 - 512)) = o;
            }
        }
    }
}

// ---------------- kernel 1: mask -> packed bits + bounding box ---------------
__global__ __launch_bounds__(256) void mask_kernel(const float* __restrict__ masks) {
    int b = blockIdx.x;
    const float* m = masks + (size_t)b * 16384;
    __shared__ unsigned words[512];
    __shared__ unsigned colOr[4];
    __shared__ unsigned rowBits[4];
    int t = threadIdx.x;
    int lane = t & 31, warp = t >> 5;

    #pragma unroll 4
    for (int it = 0; it < 64; it++) {
        int idx = it * 256 + t;
        unsigned ball = __ballot_sync(0xffffffffu, m[idx] > 0.f);
        if (lane == 0) words[it * 8 + warp] = ball;
    }
    __syncthreads();

    if (t < 4) {
        unsigned o = 0;
        for (int y = 0; y < 128; y++) o |= words[y * 4 + t];
        colOr[t] = o;
    }
    if (t < 128) {
        const unsigned* w = &words[t * 4];
        unsigned any = (w[0] | w[1] | w[2] | w[3]) != 0u;
        unsigned rb = __ballot_sync(0xffffffffu, any);
        if (lane == 0) rowBits[warp] = rb;
    }
    __syncthreads();

    if (t == 0) {
        int xmin = 128, xmax = -1, ymin = 128, ymax = -1;
        #pragma unroll
        for (int j = 0; j < 4; j++) {
            unsigned v = colOr[j];
            if (v) {
                int lo = __ffs(v) - 1 + 32 * j; if (lo < xmin) xmin = lo;
                int hi = 31 - __clz(v) + 32 * j; if (hi > xmax) xmax = hi;
            }
            unsigned r = rowBits[j];
            if (r) {
                int lo = __ffs(r) - 1 + 32 * j; if (lo < ymin) ymin = lo;
                int hi = 31 - __clz(r) + 32 * j; if (hi > ymax) ymax = hi;
            }
        }
        float4 box;
        if (xmax >= 0) {
            float x0 = xmin * (1.f/128.f), x1 = (xmax + 1) * (1.f/128.f);
            float y0 = ymin * (1.f/128.f), y1 = (ymax + 1) * (1.f/128.f);
            box = make_float4((x0 + x1) * 0.5f, (y0 + y1) * 0.5f, x1 - x0, y1 - y0);
        } else {
            box = make_float4(0.f, 0.f, 0.f, 0.f);
        }
        ((float4*)g_box)[b] = box;
    }
    unsigned* bo = g_bits + (size_t)b * 512;
    bo[t]       = words[t];
    bo[t + 256] = words[t + 256];
}

// ---------------- fp32 tiled SGEMM (small out-projection only) --------------
template<int BM, int BN, int BK, int TM, int TN>
__global__ __launch_bounds__((BM/TM)*(BN/TN))
void sgemm_kernel(const float* __restrict__ A, const float* __restrict__ B,
                  const float* __restrict__ bias,
                  float* __restrict__ Cmat, int M, int N, int K) {
    constexpr int THREADS = (BM/TM)*(BN/TN);
    __shared__ float As[BK][BM];
    __shared__ float Bs[BK][BN];
    const int block_row = blockIdx.y * BM;
    const int block_col = blockIdx.x * BN;
    const int tid  = threadIdx.x;
    const int tcol = tid % (BN/TN);
    const int trow = tid / (BN/TN);

    float acc[TM][TN];
    #pragma unroll
    for (int i = 0; i < TM; i++)
        #pragma unroll
        for (int j = 0; j < TN; j++) acc[i][j] = 0.f;

    constexpr int AV = (BM*BK)/(4*THREADS);
    constexpr int BV = (BK*BN)/(4*THREADS);

    for (int k0 = 0; k0 < K; k0 += BK) {
        #pragma unroll
        for (int i = 0; i < AV; i++) {
            int v = tid + i * THREADS;
            int r  = v / (BK/4);
            int c4 = (v % (BK/4)) * 4;
            int rg = block_row + r; if (rg > M - 1) rg = M - 1;
            float4 a = *(const float4*)(A + (size_t)rg * K + k0 + c4);
            As[c4+0][r] = a.x; As[c4+1][r] = a.y; As[c4+2][r] = a.z; As[c4+3][r] = a.w;
        }
        #pragma unroll
        for (int i = 0; i < BV; i++) {
            int v = tid + i * THREADS;
            int r  = v / (BN/4);
            int c4 = (v % (BN/4)) * 4;
            *(float4*)(&Bs[r][c4]) = *(const float4*)(B + (size_t)(k0 + r) * N + block_col + c4);
        }
        __syncthreads();

        #pragma unroll
        for (int k = 0; k < BK; k++) {
            float ra[TM], rb[TN];
            #pragma unroll
            for (int i = 0; i < TM/2; i++) {
                ra[i]        = As[k][trow*(TM/2) + i];
                ra[i + TM/2] = As[k][BM/2 + trow*(TM/2) + i];
            }
            #pragma unroll
            for (int j = 0; j < TN/2; j++) {
                rb[j]        = Bs[k][tcol*(TN/2) + j];
                rb[j + TN/2] = Bs[k][BN/2 + tcol*(TN/2) + j];
            }
            #pragma unroll
            for (int i = 0; i < TM; i++)
                #pragma unroll
                for (int j = 0; j < TN; j++)
                    acc[i][j] += ra[i] * rb[j];
        }
        __syncthreads();
    }

    #pragma unroll
    for (int i = 0; i < TM; i++) {
        int rr = (i < TM/2) ? trow*(TM/2) + i : BM/2 + trow*(TM/2) + (i - TM/2);
        int r = block_row + rr;
        if (r >= M) continue;
        #pragma unroll
        for (int j = 0; j < TN; j++) {
            int cc = (j < TN/2) ? tcol*(TN/2) + j : BN/2 + tcol*(TN/2) + (j - TN/2);
            int c = block_col + cc;
            Cmat[(size_t)r * N + c] = acc[i][j] + bias[c];
        }
    }
}

// ---------------- kernel 4: sampling + softmax + bilinear gather -------------
__global__ __launch_bounds__(256) void sample_kernel() {
    int b = blockIdx.x;
    int n = b / LQ;
    int t = threadIdx.x, lane = t & 31, h = t >> 5;
    __shared__ int   s_idx[8][32][4];
    __shared__ float s_w[8][32][4];

    const int Wl_[4]    = {128, 64, 32, 16};
    const int start_[4] = {0, 16384, 20480, 21504};

    float4 box = ((const float4*)g_box)[b];

    int p = lane, l = p >> 3;
    float ox = g_off[(size_t)b * 512 + (h * 32 + p) * 2 + 0];
    float oy = g_off[(size_t)b * 512 + (h * 32 + p) * 2 + 1];
    float locx = box.x + ox * (1.f / 16.f) * box.z;
    float locy = box.y + oy * (1.f / 16.f) * box.w;

    int px = (int)(locx * 128.f); px = min(max(px, 0), 127);
    int py = (int)(locy * 128.f); py = min(max(py, 0), 127);
    unsigned wbits = g_bits[(size_t)b * 512 + py * 4 + (px >> 5)];
    float pin = ((wbits >> (px & 31)) & 1u) ? 1.f : 0.f;

    float logit = g_attn[(size_t)b * 256 + h * 32 + p] * pin;
    float mx = logit;
    #pragma unroll
    for (int o = 16; o; o >>= 1) mx = fmaxf(mx, __shfl_xor_sync(0xffffffffu, mx, o));
    float e = expf(logit - mx);
    float sm = e;
    #pragma unroll
    for (int o = 16; o; o >>= 1) sm += __shfl_xor_sync(0xffffffffu, sm, o);
    float aw = e / sm;

    int Wl = Wl_[l], Hl = Wl;
    float pxf = locx * (float)Wl - 0.5f;
    float pyf = locy * (float)Hl - 0.5f;
    float x0f = floorf(pxf), y0f = floorf(pyf);
    float wx = pxf - x0f, wy = pyf - y0f;
    int x0 = (int)x0f, y0 = (int)y0f;
    int base = n * LEN_IN + start_[l];

    #pragma unroll
    for (int k = 0; k < 4; k++) {
        int xi = x0 + (k & 1), yi = y0 + (k >> 1);
        float cw = ((k & 1) ? wx : 1.f - wx) * ((k >> 1) ? wy : 1.f - wy);
        bool valid = (xi >= 0) && (xi < Wl) && (yi >= 0) && (yi < Hl);
        int xc = min(max(xi, 0), Wl - 1);
        int yc = min(max(yi, 0), Hl - 1);
        s_idx[h][p][k] = base + yc * Wl + xc;
        s_w[h][p][k]   = valid ? cw * aw : 0.f;
    }
    __syncwarp();

    int d = lane;
    const float* vcol = g_value + h * 32 + d;
    float acc = 0.f;
    #pragma unroll 4
    for (int pp = 0; pp < 32; pp++) {
        #pragma unroll
        for (int k = 0; k < 4; k++) {
            float wgt = s_w[h][pp][k];
            if (wgt != 0.f)
                acc += wgt * vcol[(size_t)s_idx[h][pp][k] * 256];
        }
    }
    g_samp[(size_t)b * 256 + h * 32 + d] = acc;
}

// ---------------- launch --------------------------------------------------
extern "C" void kernel_launch(void* const* d_in, const int* in_sizes, int n_in,
                              void* d_out, int out_size) {
    const float* query = (const float*)d_in[0];
    const float* masks = (const float*)d_in[2];
    const float* flat  = (const float*)d_in[4];
    const unsigned char* pad = (const unsigned char*)d_in[7];
    const float* Woff  = (const float*)d_in[8];
    const float* boff  = (const float*)d_in[9];
    const float* Wattn = (const float*)d_in[10];
    const float* battn = (const float*)d_in[11];
    const float* Wval  = (const float*)d_in[12];
    const float* bval  = (const float*)d_in[13];
    const float* Wout  = (const float*)d_in[14];
    const float* bout  = (const float*)d_in[15];
    float* out = (float*)d_out;

    float* sampp = nullptr;
    cudaGetSymbolAddress((void**)&sampp, g_samp);

    // 1) masks -> packed bits + bboxes
    mask_kernel<<<NQ, 256>>>(masks);

    // 2) weight prep (fp16 hi/lo fragment layouts)
    prep_Bval<<<64, 256>>>(Wval);
    prep_Bproj<<<192, 256>>>(Woff, Wattn);

    // 3) value = input_flatten @ W_val + b_val (2-term fp16 HMMA)
    value_gemm<<<dim3(MROWS/128, 2), 256>>>(flat, pad, bval);

    // 4) [offsets | logits] = query @ [Woff | Wattn] + bias (3-term fp16 HMMA)
    proj_gemm<<<dim3((NQ + 127)/128, 6), 256>>>(query, boff, battn);

    // 5) softmax + bilinear sampling
    sample_kernel<<<NQ, 256>>>();

    // 6) out = sampled @ W_out + b_out
    sgemm_kernel<64,64,16,4,4><<<dim3(CDIM/64, (NQ + 63)/64), 256>>>(
        sampp, Wout, bout, out, NQ, CDIM, CDIM);
}

// round 5
// speedup vs baseline: 2.9956x; 1.6413x over previous
#include <cuda_runtime.h>
#include <cuda_fp16.h>
#include <math.h>
#include <stdint.h>

// Problem constants (fixed by the dataset)
#define NB      8
#define LQ      300
#define CDIM    256
#define HEADS   8
#define NLVL    4
#define NPTS    8
#define DHEAD   32
#define LEN_IN  21760
#define NQ      (NB*LQ)         // 2400
#define MROWS   (NB*LEN_IN)     // 174080

// ---------------- scratch (device globals; no allocations allowed) ----------
__device__ __half   g_valh[(size_t)MROWS * CDIM];    // projected value (fp16), 89 MB
__device__ unsigned g_bits[NQ * 512];                // packed 128x128 bitmask per (n,q)
__device__ float    g_box[NQ * 4];                   // cx, cy, w, h
__device__ float    g_off[NQ * 512];                 // sampling offsets (h,l,p,2)
__device__ float    g_attn[NQ * 256];                // raw attention logits (h,l,p)
__device__ float    g_samp[NQ * 256];                // sampled output before W_out
// W_val^T in m16n8k16 B-fragment layout (fp16, single term).
__device__ uint2    g_Bf[32 * 16 * 32];
// [Woff | Wattn] (N=768) in B-fragment layout, fp16 hi/lo splits (3-term, exact).
__device__ uint2    g_PfHi[96 * 16 * 32];
__device__ uint2    g_PfLo[96 * 16 * 32];

// ---------------- helpers ----------------------------------------------------
__device__ __forceinline__ void mma16816(float* c, const uint32_t* a, const uint2 b) {
    asm volatile(
        "mma.sync.aligned.m16n8k16.row.col.f32.f16.f16.f32 "
        "{%0,%1,%2,%3}, {%4,%5,%6,%7}, {%8,%9}, {%0,%1,%2,%3};\n"
        : "+f"(c[0]), "+f"(c[1]), "+f"(c[2]), "+f"(c[3])
        : "r"(a[0]), "r"(a[1]), "r"(a[2]), "r"(a[3]), "r"(b.x), "r"(b.y));
}
__device__ __forceinline__ uint32_t cvt_h(float2 v) {
    __half2 h = __float22half2_rn(v);
    return *(uint32_t*)&h;
}
__device__ __forceinline__ void cvt_hilo(float2 v, uint32_t& hi, uint32_t& lo) {
    __half2 h = __float22half2_rn(v);
    float2 f = __half22float2(h);
    __half2 l = __float22half2_rn(make_float2(v.x - f.x, v.y - f.y));
    hi = *(uint32_t*)&h;
    lo = *(uint32_t*)&l;
}
__device__ __forceinline__ uint32_t smem_u32(const void* p) {
    uint32_t a;
    asm("{ .reg .u64 t; cvta.to.shared.u64 t, %1; cvt.u32.u64 %0, t; }" : "=r"(a) : "l"(p));
    return a;
}
__device__ __forceinline__ void cp_async16(uint32_t dst, const void* src) {
    asm volatile("cp.async.cg.shared.global [%0], [%1], 16;" :: "r"(dst), "l"(src));
}
__device__ __forceinline__ void cp_commit() { asm volatile("cp.async.commit_group;" ::: "memory"); }
template<int N> __device__ __forceinline__ void cp_wait() {
    asm volatile("cp.async.wait_group %0;" :: "n"(N) : "memory");
}

// ================= prep: W_val^T -> fp16 fragment layout ====================
__global__ __launch_bounds__(256) void prep_Bval(const float* __restrict__ W) {
    int idx = blockIdx.x * 256 + threadIdx.x;     // 16384 threads
    int lane  = idx & 31;
    int ks    = (idx >> 5) & 15;
    int ntile = idx >> 9;                         // 0..31
    int n  = ntile * 8 + (lane >> 2);
    int kb = ks * 16 + (lane & 3) * 2;
    float x0 = W[(kb + 0) * 256 + n];
    float x1 = W[(kb + 1) * 256 + n];
    float x2 = W[(kb + 8) * 256 + n];
    float x3 = W[(kb + 9) * 256 + n];
    g_Bf[idx] = make_uint2(cvt_h(make_float2(x0, x1)), cvt_h(make_float2(x2, x3)));
}

// ================= prep: [Woff | Wattn]^T -> fp16 hi/lo fragments ===========
__global__ __launch_bounds__(256) void prep_Bproj(
        const float* __restrict__ Woff, const float* __restrict__ Wattn) {
    int idx = blockIdx.x * 256 + threadIdx.x;     // 49152 threads
    int lane  = idx & 31;
    int ks    = (idx >> 5) & 15;
    int ntile = idx >> 9;                         // 0..95
    int n  = ntile * 8 + (lane >> 2);             // 0..767
    int kb = ks * 16 + (lane & 3) * 2;
    float x[4];
    #pragma unroll
    for (int q = 0; q < 4; q++) {
        int k = kb + (q >> 1) * 8 + (q & 1);
        x[q] = (n < 512) ? Woff[k * 512 + n] : Wattn[k * 256 + (n - 512)];
    }
    uint32_t h0, l0, h1, l1;
    cvt_hilo(make_float2(x[0], x[1]), h0, l0);
    cvt_hilo(make_float2(x[2], x[3]), h1, l1);
    g_PfHi[idx] = make_uint2(h0, h1);
    g_PfLo[idx] = make_uint2(l0, l1);
}

// ================= kernel: fp16 HMMA value GEMM (64x256 CTA tile) ===========
// 8 warps: 2(M)x4(N), warp tile 32x64. A staged via 3-deep cp.async pipeline.
// value = fp16(A) @ fp16(W_val^T) + bias, stored as fp16.
#define SROWF   68                      // floats per smem row (64 + 4 pad)
#define STAGEF  (64 * SROWF)            // floats per stage
#define VG_SMEM (3 * STAGEF * 4)        // 52224 bytes

__global__ __launch_bounds__(256, 2) void value_gemm(
        const float* __restrict__ A, const unsigned char* __restrict__ pad,
        const float* __restrict__ bias) {
    extern __shared__ float smf[];
    const uint32_t sb = smem_u32(smf);
    const int tid = threadIdx.x, lane = tid & 31, wid = tid >> 5;
    const int g = lane >> 2, t = lane & 3;
    const int wm = (wid >> 2) * 32;          // warp M offset (0/32)
    const int wn = (wid & 3) * 64;           // warp N offset (0/64/128/192)
    const int rowTile = blockIdx.x * 64;
    const int ntb = wn >> 3;

    float2 bias2[8];
    #pragma unroll
    for (int j = 0; j < 8; j++)
        bias2[j] = *(const float2*)(bias + wn + j * 8 + t * 2);

    float acc[2][8][4];
    #pragma unroll
    for (int i = 0; i < 2; i++)
        #pragma unroll
        for (int j = 0; j < 8; j++)
            #pragma unroll
            for (int q = 0; q < 4; q++) acc[i][j][q] = 0.f;

    // issue chunk c (64 k-cols) into stage s
    #define ISSUE_A(c, s) { \
        _Pragma("unroll") \
        for (int u4 = 0; u4 < 4; u4++) { \
            int u = tid + u4 * 256; \
            int row = u >> 4, seg = u & 15; \
            cp_async16(sb + ((s) * STAGEF + row * SROWF + seg * 4) * 4, \
                       A + (size_t)(rowTile + row) * 256 + (c) * 64 + seg * 4); \
        } \
        cp_commit(); }

    ISSUE_A(0, 0);
    ISSUE_A(1, 1);

    #pragma unroll
    for (int c = 0; c < 4; c++) {
        if (c < 3) cp_wait<1>(); else cp_wait<0>();
        __syncthreads();
        if (c < 2) ISSUE_A(c + 2, (c + 2) % 3);

        const float* st = smf + (c % 3) * STAGEF;
        #pragma unroll
        for (int ksl = 0; ksl < 4; ksl++) {
            const int ks = c * 4 + ksl;
            uint2 b[8];
            #pragma unroll
            for (int j = 0; j < 8; j++)
                b[j] = g_Bf[((ntb + j) * 16 + ks) * 32 + lane];

            uint32_t ah[2][4];
            #pragma unroll
            for (int i = 0; i < 2; i++) {
                const float* ap = st + (wm + i * 16 + g) * SROWF + ksl * 16 + t * 2;
                ah[i][0] = cvt_h(*(const float2*)(ap));
                ah[i][1] = cvt_h(*(const float2*)(ap + 8 * SROWF));
                ah[i][2] = cvt_h(*(const float2*)(ap + 8));
                ah[i][3] = cvt_h(*(const float2*)(ap + 8 * SROWF + 8));
            }
            #pragma unroll
            for (int i = 0; i < 2; i++)
                #pragma unroll
                for (int j = 0; j < 8; j++)
                    mma16816(acc[i][j], ah[i], b[j]);
        }
    }
    #undef ISSUE_A

    // ---- epilogue: bias add, padding zero, fp16 stores
    #pragma unroll
    for (int i = 0; i < 2; i++) {
        int ra = rowTile + wm + i * 16 + g;
        int rb = ra + 8;
        bool pa = pad[ra] != 0, pb = pad[rb] != 0;
        #pragma unroll
        for (int j = 0; j < 8; j++) {
            int c0 = wn + j * 8 + t * 2;
            float2 oa, ob;
            oa.x = pa ? 0.f : acc[i][j][0] + bias2[j].x;
            oa.y = pa ? 0.f : acc[i][j][1] + bias2[j].y;
            ob.x = pb ? 0.f : acc[i][j][2] + bias2[j].x;
            ob.y = pb ? 0.f : acc[i][j][3] + bias2[j].y;
            *(__half2*)(g_valh + (size_t)ra * 256 + c0) = __float22half2_rn(oa);
            *(__half2*)(g_valh + (size_t)rb * 256 + c0) = __float22half2_rn(ob);
        }
    }
}

// ================= kernel: HMMA 3-term fp16 proj GEMM =======================
__global__ __launch_bounds__(256) void proj_gemm(
        const float* __restrict__ Q,
        const float* __restrict__ boff, const float* __restrict__ battn) {
    const int tid = threadIdx.x, lane = tid & 31, wid = tid >> 5;
    const int g = lane >> 2, t = lane & 3;
    const int rowBase = blockIdx.x * 128 + (wid & 3) * 32 + g;
    const int colBase = blockIdx.y * 128 + (wid >> 2) * 64;
    const int ntb = colBase >> 3;

    float2 bias2[8];
    #pragma unroll
    for (int j = 0; j < 8; j++) {
        int c = colBase + j * 8 + t * 2;
        bias2[j] = (c < 512) ? *(const float2*)(boff + c)
                             : *(const float2*)(battn + (c - 512));
    }

    float acc[2][8][4];
    #pragma unroll
    for (int i = 0; i < 2; i++)
        #pragma unroll
        for (int j = 0; j < 8; j++)
            #pragma unroll
            for (int q = 0; q < 4; q++) acc[i][j][q] = 0.f;

    float2 araw[2][2][4];
    #define LOAD_AQ(ks, buf) { \
        _Pragma("unroll") \
        for (int i = 0; i < 2; i++) { \
            int r0 = min(rowBase + i * 16, NQ - 1); \
            int r1 = min(rowBase + i * 16 + 8, NQ - 1); \
            const float* b0 = Q + (size_t)r0 * 256 + (ks) * 16 + t * 2; \
            const float* b1 = Q + (size_t)r1 * 256 + (ks) * 16 + t * 2; \
            araw[buf][i][0] = *(const float2*)(b0); \
            araw[buf][i][1] = *(const float2*)(b1); \
            araw[buf][i][2] = *(const float2*)(b0 + 8); \
            araw[buf][i][3] = *(const float2*)(b1 + 8); \
        } }

    LOAD_AQ(0, 0);
    #pragma unroll
    for (int ks = 0; ks < 16; ks++) {
        const int cur = ks & 1;
        if (ks < 15) LOAD_AQ(ks + 1, cur ^ 1);

        uint2 bhi[8], blo[8];
        #pragma unroll
        for (int j = 0; j < 8; j++) {
            int bidx = ((ntb + j) * 16 + ks) * 32 + lane;
            bhi[j] = g_PfHi[bidx];
            blo[j] = g_PfLo[bidx];
        }
        uint32_t ahi[2][4], alo[2][4];
        #pragma unroll
        for (int i = 0; i < 2; i++)
            #pragma unroll
            for (int q = 0; q < 4; q++)
                cvt_hilo(araw[cur][i][q], ahi[i][q], alo[i][q]);

        #pragma unroll
        for (int i = 0; i < 2; i++)
            #pragma unroll
            for (int j = 0; j < 8; j++) {
                mma16816(acc[i][j], ahi[i], bhi[j]);
                mma16816(acc[i][j], ahi[i], blo[j]);
                mma16816(acc[i][j], alo[i], bhi[j]);
            }
    }
    #undef LOAD_AQ

    #pragma unroll
    for (int i = 0; i < 2; i++) {
        #pragma unroll
        for (int q2 = 0; q2 < 2; q2++) {
            int r = rowBase + i * 16 + q2 * 8;
            if (r >= NQ) continue;
            #pragma unroll
            for (int j = 0; j < 8; j++) {
                int c0 = colBase + j * 8 + t * 2;
                float2 o;
                o.x = acc[i][j][q2 * 2 + 0] + bias2[j].x;
                o.y = acc[i][j][q2 * 2 + 1] + bias2[j].y;
                if (c0 < 512) *(float2*)(g_off  + (size_t)r * 512 + c0)         = o;
                else          *(float2*)(g_attn + (size_t)r * 256 + (c0 - 512)) = o;
            }
        }
    }
}

// ---------------- kernel 1: mask -> packed bits + bounding box ---------------
__global__ __launch_bounds__(256) void mask_kernel(const float* __restrict__ masks) {
    int b = blockIdx.x;
    const float* m = masks + (size_t)b * 16384;
    __shared__ unsigned words[512];
    __shared__ unsigned colOr[4];
    __shared__ unsigned rowBits[4];
    int t = threadIdx.x;
    int lane = t & 31, warp = t >> 5;

    #pragma unroll 4
    for (int it = 0; it < 64; it++) {
        int idx = it * 256 + t;
        unsigned ball = __ballot_sync(0xffffffffu, m[idx] > 0.f);
        if (lane == 0) words[it * 8 + warp] = ball;
    }
    __syncthreads();

    if (t < 4) {
        unsigned o = 0;
        for (int y = 0; y < 128; y++) o |= words[y * 4 + t];
        colOr[t] = o;
    }
    if (t < 128) {
        const unsigned* w = &words[t * 4];
        unsigned any = (w[0] | w[1] | w[2] | w[3]) != 0u;
        unsigned rb = __ballot_sync(0xffffffffu, any);
        if (lane == 0) rowBits[warp] = rb;
    }
    __syncthreads();

    if (t == 0) {
        int xmin = 128, xmax = -1, ymin = 128, ymax = -1;
        #pragma unroll
        for (int j = 0; j < 4; j++) {
            unsigned v = colOr[j];
            if (v) {
                int lo = __ffs(v) - 1 + 32 * j; if (lo < xmin) xmin = lo;
                int hi = 31 - __clz(v) + 32 * j; if (hi > xmax) xmax = hi;
            }
            unsigned r = rowBits[j];
            if (r) {
                int lo = __ffs(r) - 1 + 32 * j; if (lo < ymin) ymin = lo;
                int hi = 31 - __clz(r) + 32 * j; if (hi > ymax) ymax = hi;
            }
        }
        float4 box;
        if (xmax >= 0) {
            float x0 = xmin * (1.f/128.f), x1 = (xmax + 1) * (1.f/128.f);
            float y0 = ymin * (1.f/128.f), y1 = (ymax + 1) * (1.f/128.f);
            box = make_float4((x0 + x1) * 0.5f, (y0 + y1) * 0.5f, x1 - x0, y1 - y0);
        } else {
            box = make_float4(0.f, 0.f, 0.f, 0.f);
        }
        ((float4*)g_box)[b] = box;
    }
    unsigned* bo = g_bits + (size_t)b * 512;
    bo[t]       = words[t];
    bo[t + 256] = words[t + 256];
}

// ---------------- fp32 tiled SGEMM (small out-projection only) --------------
template<int BM, int BN, int BK, int TM, int TN>
__global__ __launch_bounds__((BM/TM)*(BN/TN))
void sgemm_kernel(const float* __restrict__ A, const float* __restrict__ B,
                  const float* __restrict__ bias,
                  float* __restrict__ Cmat, int M, int N, int K) {
    constexpr int THREADS = (BM/TM)*(BN/TN);
    __shared__ float As[BK][BM];
    __shared__ float Bs[BK][BN];
    const int block_row = blockIdx.y * BM;
    const int block_col = blockIdx.x * BN;
    const int tid  = threadIdx.x;
    const int tcol = tid % (BN/TN);
    const int trow = tid / (BN/TN);

    float acc[TM][TN];
    #pragma unroll
    for (int i = 0; i < TM; i++)
        #pragma unroll
        for (int j = 0; j < TN; j++) acc[i][j] = 0.f;

    constexpr int AV = (BM*BK)/(4*THREADS);
    constexpr int BV = (BK*BN)/(4*THREADS);

    for (int k0 = 0; k0 < K; k0 += BK) {
        #pragma unroll
        for (int i = 0; i < AV; i++) {
            int v = tid + i * THREADS;
            int r  = v / (BK/4);
            int c4 = (v % (BK/4)) * 4;
            int rg = block_row + r; if (rg > M - 1) rg = M - 1;
            float4 a = *(const float4*)(A + (size_t)rg * K + k0 + c4);
            As[c4+0][r] = a.x; As[c4+1][r] = a.y; As[c4+2][r] = a.z; As[c4+3][r] = a.w;
        }
        #pragma unroll
        for (int i = 0; i < BV; i++) {
            int v = tid + i * THREADS;
            int r  = v / (BN/4);
            int c4 = (v % (BN/4)) * 4;
            *(float4*)(&Bs[r][c4]) = *(const float4*)(B + (size_t)(k0 + r) * N + block_col + c4);
        }
        __syncthreads();

        #pragma unroll
        for (int k = 0; k < BK; k++) {
            float ra[TM], rb[TN];
            #pragma unroll
            for (int i = 0; i < TM/2; i++) {
                ra[i]        = As[k][trow*(TM/2) + i];
                ra[i + TM/2] = As[k][BM/2 + trow*(TM/2) + i];
            }
            #pragma unroll
            for (int j = 0; j < TN/2; j++) {
                rb[j]        = Bs[k][tcol*(TN/2) + j];
                rb[j + TN/2] = Bs[k][BN/2 + tcol*(TN/2) + j];
            }
            #pragma unroll
            for (int i = 0; i < TM; i++)
                #pragma unroll
                for (int j = 0; j < TN; j++)
                    acc[i][j] += ra[i] * rb[j];
        }
        __syncthreads();
    }

    #pragma unroll
    for (int i = 0; i < TM; i++) {
        int rr = (i < TM/2) ? trow*(TM/2) + i : BM/2 + trow*(TM/2) + (i - TM/2);
        int r = block_row + rr;
        if (r >= M) continue;
        #pragma unroll
        for (int j = 0; j < TN; j++) {
            int cc = (j < TN/2) ? tcol*(TN/2) + j : BN/2 + tcol*(TN/2) + (j - TN/2);
            int c = block_col + cc;
            Cmat[(size_t)r * N + c] = acc[i][j] + bias[c];
        }
    }
}

// ---------------- kernel 4: sampling + softmax + bilinear gather -------------
__global__ __launch_bounds__(256) void sample_kernel() {
    int b = blockIdx.x;
    int n = b / LQ;
    int t = threadIdx.x, lane = t & 31, h = t >> 5;
    __shared__ int   s_idx[8][32][4];
    __shared__ float s_w[8][32][4];

    const int Wl_[4]    = {128, 64, 32, 16};
    const int start_[4] = {0, 16384, 20480, 21504};

    float4 box = ((const float4*)g_box)[b];

    int p = lane, l = p >> 3;
    float ox = g_off[(size_t)b * 512 + (h * 32 + p) * 2 + 0];
    float oy = g_off[(size_t)b * 512 + (h * 32 + p) * 2 + 1];
    float locx = box.x + ox * (1.f / 16.f) * box.z;
    float locy = box.y + oy * (1.f / 16.f) * box.w;

    int px = (int)(locx * 128.f); px = min(max(px, 0), 127);
    int py = (int)(locy * 128.f); py = min(max(py, 0), 127);
    unsigned wbits = g_bits[(size_t)b * 512 + py * 4 + (px >> 5)];
    float pin = ((wbits >> (px & 31)) & 1u) ? 1.f : 0.f;

    float logit = g_attn[(size_t)b * 256 + h * 32 + p] * pin;
    float mx = logit;
    #pragma unroll
    for (int o = 16; o; o >>= 1) mx = fmaxf(mx, __shfl_xor_sync(0xffffffffu, mx, o));
    float e = expf(logit - mx);
    float sm = e;
    #pragma unroll
    for (int o = 16; o; o >>= 1) sm += __shfl_xor_sync(0xffffffffu, sm, o);
    float aw = e / sm;

    int Wl = Wl_[l], Hl = Wl;
    float pxf = locx * (float)Wl - 0.5f;
    float pyf = locy * (float)Hl - 0.5f;
    float x0f = floorf(pxf), y0f = floorf(pyf);
    float wx = pxf - x0f, wy = pyf - y0f;
    int x0 = (int)x0f, y0 = (int)y0f;
    int base = n * LEN_IN + start_[l];

    #pragma unroll
    for (int k = 0; k < 4; k++) {
        int xi = x0 + (k & 1), yi = y0 + (k >> 1);
        float cw = ((k & 1) ? wx : 1.f - wx) * ((k >> 1) ? wy : 1.f - wy);
        bool valid = (xi >= 0) && (xi < Wl) && (yi >= 0) && (yi < Hl);
        int xc = min(max(xi, 0), Wl - 1);
        int yc = min(max(yi, 0), Hl - 1);
        s_idx[h][p][k] = base + yc * Wl + xc;
        s_w[h][p][k]   = valid ? cw * aw : 0.f;
    }
    __syncwarp();

    int d = lane;
    const __half* vcol = g_valh + h * 32 + d;
    float acc = 0.f;
    #pragma unroll 4
    for (int pp = 0; pp < 32; pp++) {
        #pragma unroll
        for (int k = 0; k < 4; k++) {
            float wgt = s_w[h][pp][k];
            if (wgt != 0.f)
                acc += wgt * __half2float(vcol[(size_t)s_idx[h][pp][k] * 256]);
        }
    }
    g_samp[(size_t)b * 256 + h * 32 + d] = acc;
}

// ---------------- launch --------------------------------------------------
extern "C" void kernel_launch(void* const* d_in, const int* in_sizes, int n_in,
                              void* d_out, int out_size) {
    const float* query = (const float*)d_in[0];
    const float* masks = (const float*)d_in[2];
    const float* flat  = (const float*)d_in[4];
    const unsigned char* pad = (const unsigned char*)d_in[7];
    const float* Woff  = (const float*)d_in[8];
    const float* boff  = (const float*)d_in[9];
    const float* Wattn = (const float*)d_in[10];
    const float* battn = (const float*)d_in[11];
    const float* Wval  = (const float*)d_in[12];
    const float* bval  = (const float*)d_in[13];
    const float* Wout  = (const float*)d_in[14];
    const float* bout  = (const float*)d_in[15];
    float* out = (float*)d_out;

    float* sampp = nullptr;
    cudaGetSymbolAddress((void**)&sampp, g_samp);

    cudaFuncSetAttribute(value_gemm, cudaFuncAttributeMaxDynamicSharedMemorySize, VG_SMEM);

    // 1) masks -> packed bits + bboxes
    mask_kernel<<<NQ, 256>>>(masks);

    // 2) weight prep
    prep_Bval<<<64, 256>>>(Wval);
    prep_Bproj<<<192, 256>>>(Woff, Wattn);

    // 3) value = input_flatten @ W_val + b_val (1-term fp16 HMMA, fp16 out)
    value_gemm<<<MROWS/64, 256, VG_SMEM>>>(flat, pad, bval);

    // 4) [offsets | logits] = query @ [Woff | Wattn] + bias (3-term fp16 HMMA)
    proj_gemm<<<dim3((NQ + 127)/128, 6), 256>>>(query, boff, battn);

    // 5) softmax + bilinear sampling
    sample_kernel<<<NQ, 256>>>();

    // 6) out = sampled @ W_out + b_out
    sgemm_kernel<64,64,16,4,4><<<dim3(CDIM/64, (NQ + 63)/64), 256>>>(
        sampp, Wout, bout, out, NQ, CDIM, CDIM);
}

// round 6
// speedup vs baseline: 3.0009x; 1.0018x over previous
#include <cuda_runtime.h>
#include <cuda_fp16.h>
#include <math.h>
#include <stdint.h>

// Problem constants (fixed by the dataset)
#define NB      8
#define LQ      300
#define CDIM    256
#define HEADS   8
#define NLVL    4
#define NPTS    8
#define DHEAD   32
#define LEN_IN  21760
#define NQ      (NB*LQ)         // 2400
#define MROWS   (NB*LEN_IN)     // 174080

// ---------------- scratch (device globals; no allocations allowed) ----------
__device__ __half   g_valh[(size_t)MROWS * CDIM];    // projected value (fp16), 89 MB
__device__ unsigned g_bits[NQ * 512];                // packed mask: word=(y*4+(x&3)), bit=x>>2
__device__ float    g_box[NQ * 4];                   // cx, cy, w, h
__device__ float    g_off[NQ * 512];                 // sampling offsets (h,l,p,2)
__device__ float    g_attn[NQ * 256];                // raw attention logits (h,l,p)
__device__ float    g_samp[NQ * 256];                // sampled output before W_out
// W_val^T fragments: ((ntile*8 + kpair)*32 + lane) -> uint4 {ks even b0,b1, ks odd b0,b1}
__device__ uint4    g_Bf4[32 * 8 * 32];
// [Woff | Wattn] (N=768) in B-fragment layout, fp16 hi/lo splits (3-term, exact).
__device__ uint2    g_PfHi[96 * 16 * 32];
__device__ uint2    g_PfLo[96 * 16 * 32];

// ---------------- helpers ----------------------------------------------------
__device__ __forceinline__ void mma16816(float* c, const uint32_t* a, const uint2 b) {
    asm volatile(
        "mma.sync.aligned.m16n8k16.row.col.f32.f16.f16.f32 "
        "{%0,%1,%2,%3}, {%4,%5,%6,%7}, {%8,%9}, {%0,%1,%2,%3};\n"
        : "+f"(c[0]), "+f"(c[1]), "+f"(c[2]), "+f"(c[3])
        : "r"(a[0]), "r"(a[1]), "r"(a[2]), "r"(a[3]), "r"(b.x), "r"(b.y));
}
__device__ __forceinline__ uint32_t cvt_h(float2 v) {
    __half2 h = __float22half2_rn(v);
    return *(uint32_t*)&h;
}
__device__ __forceinline__ void cvt_hilo(float2 v, uint32_t& hi, uint32_t& lo) {
    __half2 h = __float22half2_rn(v);
    float2 f = __half22float2(h);
    __half2 l = __float22half2_rn(make_float2(v.x - f.x, v.y - f.y));
    hi = *(uint32_t*)&h;
    lo = *(uint32_t*)&l;
}
__device__ __forceinline__ uint32_t smem_u32(const void* p) {
    uint32_t a;
    asm("{ .reg .u64 t; cvta.to.shared.u64 t, %1; cvt.u32.u64 %0, t; }" : "=r"(a) : "l"(p));
    return a;
}
__device__ __forceinline__ void cp_async16(uint32_t dst, const void* src) {
    asm volatile("cp.async.cg.shared.global [%0], [%1], 16;" :: "r"(dst), "l"(src));
}
__device__ __forceinline__ void cp_commit() { asm volatile("cp.async.commit_group;" ::: "memory"); }
template<int N> __device__ __forceinline__ void cp_wait() {
    asm volatile("cp.async.wait_group %0;" :: "n"(N) : "memory");
}
__device__ __forceinline__ void ldm_x4(uint32_t* r, uint32_t addr) {
    asm volatile("ldmatrix.sync.aligned.m8n8.x4.shared.b16 {%0,%1,%2,%3}, [%4];"
        : "=r"(r[0]), "=r"(r[1]), "=r"(r[2]), "=r"(r[3]) : "r"(addr));
}

// ================= prep: W_val^T -> fp16 uint4 fragment pairs ===============
__global__ __launch_bounds__(256) void prep_Bval(const float* __restrict__ W) {
    int idx = blockIdx.x * 256 + threadIdx.x;     // 8192 threads
    int lane  = idx & 31;
    int gkp   = (idx >> 5) & 7;                   // k-pair 0..7
    int ntile = idx >> 8;                         // 0..31
    int n  = ntile * 8 + (lane >> 2);
    uint32_t r[4];
    #pragma unroll
    for (int h2 = 0; h2 < 2; h2++) {
        int kb = (gkp * 2 + h2) * 16 + (lane & 3) * 2;
        r[h2*2+0] = cvt_h(make_float2(W[(kb + 0) * 256 + n], W[(kb + 1) * 256 + n]));
        r[h2*2+1] = cvt_h(make_float2(W[(kb + 8) * 256 + n], W[(kb + 9) * 256 + n]));
    }
    g_Bf4[idx] = make_uint4(r[0], r[1], r[2], r[3]);
}

// ================= prep: [Woff | Wattn]^T -> fp16 hi/lo fragments ===========
__global__ __launch_bounds__(256) void prep_Bproj(
        const float* __restrict__ Woff, const float* __restrict__ Wattn) {
    int idx = blockIdx.x * 256 + threadIdx.x;     // 49152 threads
    int lane  = idx & 31;
    int ks    = (idx >> 5) & 15;
    int ntile = idx >> 9;                         // 0..95
    int n  = ntile * 8 + (lane >> 2);             // 0..767
    int kb = ks * 16 + (lane & 3) * 2;
    float x[4];
    #pragma unroll
    for (int q = 0; q < 4; q++) {
        int k = kb + (q >> 1) * 8 + (q & 1);
        x[q] = (n < 512) ? Woff[k * 512 + n] : Wattn[k * 256 + (n - 512)];
    }
    uint32_t h0, l0, h1, l1;
    cvt_hilo(make_float2(x[0], x[1]), h0, l0);
    cvt_hilo(make_float2(x[2], x[3]), h1, l1);
    g_PfHi[idx] = make_uint2(h0, h1);
    g_PfLo[idx] = make_uint2(l0, l1);
}

// ================= kernel: fp16 HMMA value GEMM (64x256 CTA tile) ===========
// 8 warps: 2(M)x4(N), warp tile 32x64. fp32 A staged via 3-deep cp.async,
// cooperatively converted to an fp16 smem tile, consumed via ldmatrix.x4.
#define SROWF   68                       // floats per fp32 stage row (64 + 4 pad)
#define STAGEF  (64 * SROWF)             // floats per stage
#define HROW    72                       // halves per fp16 row (144 B, conflict-free)
#define HBUF_B  (64 * HROW * 2)          // 9216 bytes
#define VG_SMEM (3 * STAGEF * 4 + HBUF_B)  // 61440 bytes

__global__ __launch_bounds__(256, 2) void value_gemm(
        const float* __restrict__ A, const unsigned char* __restrict__ pad,
        const float* __restrict__ bias) {
    extern __shared__ float smf[];
    __half* smh = (__half*)(smf + 3 * STAGEF);
    const uint32_t sb  = smem_u32(smf);
    const uint32_t sbh = smem_u32(smh);
    const int tid = threadIdx.x, lane = tid & 31, wid = tid >> 5;
    const int g = lane >> 2, t = lane & 3;
    const int wm = (wid >> 2) * 32;          // warp M offset (0/32)
    const int wn = (wid & 3) * 64;           // warp N offset
    const int rowTile = blockIdx.x * 64;
    const int ntb = wn >> 3;

    float acc[2][8][4];
    #pragma unroll
    for (int i = 0; i < 2; i++)
        #pragma unroll
        for (int j = 0; j < 8; j++)
            #pragma unroll
            for (int q = 0; q < 4; q++) acc[i][j][q] = 0.f;

    #define ISSUE_A(c, s) { \
        _Pragma("unroll") \
        for (int u4 = 0; u4 < 4; u4++) { \
            int u = tid + u4 * 256; \
            int row = u >> 4, seg = u & 15; \
            cp_async16(sb + ((s) * STAGEF + row * SROWF + seg * 4) * 4, \
                       A + (size_t)(rowTile + row) * 256 + (c) * 64 + seg * 4); \
        } \
        cp_commit(); }

    ISSUE_A(0, 0);
    ISSUE_A(1, 1);

    const int crow = tid >> 2, ccg = tid & 3;        // convert-phase mapping

    #pragma unroll
    for (int c = 0; c < 4; c++) {
        if (c < 3) cp_wait<1>(); else cp_wait<0>();
        __syncthreads();                              // stage ready + hbuf free

        // ---- cooperative fp32 -> fp16 conversion into ldmatrix-layout tile
        {
            const float* src = smf + (c % 3) * STAGEF + crow * SROWF + ccg * 16;
            uint32_t h[8];
            #pragma unroll
            for (int i = 0; i < 8; i++)
                h[i] = cvt_h(make_float2(src[2*i], src[2*i+1]));
            uint4* dst = (uint4*)(smh + crow * HROW + ccg * 16);
            dst[0] = make_uint4(h[0], h[1], h[2], h[3]);
            dst[1] = make_uint4(h[4], h[5], h[6], h[7]);
        }
        __syncthreads();
        if (c < 2) ISSUE_A(c + 2, (c + 2) % 3);

        // ---- MMA phase: A via ldmatrix, B via uint4 LDG (2 k-steps/load)
        #pragma unroll
        for (int kp = 0; kp < 2; kp++) {
            uint4 b4[8];
            #pragma unroll
            for (int j = 0; j < 8; j++)
                b4[j] = g_Bf4[((ntb + j) * 8 + c * 2 + kp) * 32 + lane];
            #pragma unroll
            for (int h2 = 0; h2 < 2; h2++) {
                const int ksl = kp * 2 + h2;
                uint32_t a[2][4];
                #pragma unroll
                for (int i = 0; i < 2; i++) {
                    int lrow = wm + i * 16 + (lane & 15);
                    ldm_x4(a[i], sbh + lrow * (HROW * 2) + ksl * 32 + ((lane >> 4) << 4));
                }
                #pragma unroll
                for (int i = 0; i < 2; i++)
                    #pragma unroll
                    for (int j = 0; j < 8; j++)
                        mma16816(acc[i][j], a[i],
                                 h2 ? make_uint2(b4[j].z, b4[j].w)
                                    : make_uint2(b4[j].x, b4[j].y));
            }
        }
    }
    #undef ISSUE_A

    // ---- epilogue: bias add, padding zero, fp16 stores
    #pragma unroll
    for (int i = 0; i < 2; i++) {
        int ra = rowTile + wm + i * 16 + g;
        int rb = ra + 8;
        bool pa = pad[ra] != 0, pb = pad[rb] != 0;
        #pragma unroll
        for (int j = 0; j < 8; j++) {
            int c0 = wn + j * 8 + t * 2;
            float2 bi = *(const float2*)(bias + c0);
            float2 oa, ob;
            oa.x = pa ? 0.f : acc[i][j][0] + bi.x;
            oa.y = pa ? 0.f : acc[i][j][1] + bi.y;
            ob.x = pb ? 0.f : acc[i][j][2] + bi.x;
            ob.y = pb ? 0.f : acc[i][j][3] + bi.y;
            *(__half2*)(g_valh + (size_t)ra * 256 + c0) = __float22half2_rn(oa);
            *(__half2*)(g_valh + (size_t)rb * 256 + c0) = __float22half2_rn(ob);
        }
    }
}

// ================= kernel: HMMA 3-term fp16 proj GEMM =======================
__global__ __launch_bounds__(256) void proj_gemm(
        const float* __restrict__ Q,
        const float* __restrict__ boff, const float* __restrict__ battn) {
    const int tid = threadIdx.x, lane = tid & 31, wid = tid >> 5;
    const int g = lane >> 2, t = lane & 3;
    const int rowBase = blockIdx.x * 128 + (wid & 3) * 32 + g;
    const int colBase = blockIdx.y * 128 + (wid >> 2) * 64;
    const int ntb = colBase >> 3;

    float2 bias2[8];
    #pragma unroll
    for (int j = 0; j < 8; j++) {
        int c = colBase + j * 8 + t * 2;
        bias2[j] = (c < 512) ? *(const float2*)(boff + c)
                             : *(const float2*)(battn + (c - 512));
    }

    float acc[2][8][4];
    #pragma unroll
    for (int i = 0; i < 2; i++)
        #pragma unroll
        for (int j = 0; j < 8; j++)
            #pragma unroll
            for (int q = 0; q < 4; q++) acc[i][j][q] = 0.f;

    float2 araw[2][2][4];
    #define LOAD_AQ(ks, buf) { \
        _Pragma("unroll") \
        for (int i = 0; i < 2; i++) { \
            int r0 = min(rowBase + i * 16, NQ - 1); \
            int r1 = min(rowBase + i * 16 + 8, NQ - 1); \
            const float* b0 = Q + (size_t)r0 * 256 + (ks) * 16 + t * 2; \
            const float* b1 = Q + (size_t)r1 * 256 + (ks) * 16 + t * 2; \
            araw[buf][i][0] = *(const float2*)(b0); \
            araw[buf][i][1] = *(const float2*)(b1); \
            araw[buf][i][2] = *(const float2*)(b0 + 8); \
            araw[buf][i][3] = *(const float2*)(b1 + 8); \
        } }

    LOAD_AQ(0, 0);
    #pragma unroll
    for (int ks = 0; ks < 16; ks++) {
        const int cur = ks & 1;
        if (ks < 15) LOAD_AQ(ks + 1, cur ^ 1);

        uint2 bhi[8], blo[8];
        #pragma unroll
        for (int j = 0; j < 8; j++) {
            int bidx = ((ntb + j) * 16 + ks) * 32 + lane;
            bhi[j] = g_PfHi[bidx];
            blo[j] = g_PfLo[bidx];
        }
        uint32_t ahi[2][4], alo[2][4];
        #pragma unroll
        for (int i = 0; i < 2; i++)
            #pragma unroll
            for (int q = 0; q < 4; q++)
                cvt_hilo(araw[cur][i][q], ahi[i][q], alo[i][q]);

        #pragma unroll
        for (int i = 0; i < 2; i++)
            #pragma unroll
            for (int j = 0; j < 8; j++) {
                mma16816(acc[i][j], ahi[i], bhi[j]);
                mma16816(acc[i][j], ahi[i], blo[j]);
                mma16816(acc[i][j], alo[i], bhi[j]);
            }
    }
    #undef LOAD_AQ

    #pragma unroll
    for (int i = 0; i < 2; i++) {
        #pragma unroll
        for (int q2 = 0; q2 < 2; q2++) {
            int r = rowBase + i * 16 + q2 * 8;
            if (r >= NQ) continue;
            #pragma unroll
            for (int j = 0; j < 8; j++) {
                int c0 = colBase + j * 8 + t * 2;
                float2 o;
                o.x = acc[i][j][q2 * 2 + 0] + bias2[j].x;
                o.y = acc[i][j][q2 * 2 + 1] + bias2[j].y;
                if (c0 < 512) *(float2*)(g_off  + (size_t)r * 512 + c0)         = o;
                else          *(float2*)(g_attn + (size_t)r * 256 + (c0 - 512)) = o;
            }
        }
    }
}

// ---------------- kernel 1: mask -> packed bits + bounding box ---------------
// Warp processes one full 128-col row per iter via float4. Bit layout (ours):
// word (y*4 + (x&3)), bit (x>>2).
__global__ __launch_bounds__(256) void mask_kernel(const float* __restrict__ masks) {
    int b = blockIdx.x;
    const float4* m = (const float4*)(masks + (size_t)b * 16384);
    __shared__ unsigned colOrW[8][4];
    __shared__ unsigned char rowAny[128];
    __shared__ unsigned rowBits[4];
    int t = threadIdx.x, lane = t & 31, w = t >> 5;
    unsigned co[4] = {0, 0, 0, 0};
    unsigned* bo = g_bits + (size_t)b * 512;

    #pragma unroll
    for (int it = 0; it < 16; it++) {
        int row = it * 8 + w;
        float4 v = m[row * 32 + lane];
        unsigned b0 = __ballot_sync(0xffffffffu, v.x > 0.f);
        unsigned b1 = __ballot_sync(0xffffffffu, v.y > 0.f);
        unsigned b2 = __ballot_sync(0xffffffffu, v.z > 0.f);
        unsigned b3 = __ballot_sync(0xffffffffu, v.w > 0.f);
        co[0] |= b0; co[1] |= b1; co[2] |= b2; co[3] |= b3;
        if (lane == 0) rowAny[row] = ((b0 | b1 | b2 | b3) != 0u);
        if (lane < 4) {
            unsigned bb = (lane == 0) ? b0 : (lane == 1) ? b1 : (lane == 2) ? b2 : b3;
            bo[row * 4 + lane] = bb;
        }
    }
    if (lane < 4)
        colOrW[w][lane] = (lane == 0) ? co[0] : (lane == 1) ? co[1] : (lane == 2) ? co[2] : co[3];
    __syncthreads();

    if (t < 128) {
        unsigned rb = __ballot_sync(0xffffffffu, rowAny[t] != 0);
        if (lane == 0) rowBits[t >> 5] = rb;
    }
    __syncthreads();

    if (t == 0) {
        int xmin = 128, xmax = -1, ymin = 128, ymax = -1;
        #pragma unroll
        for (int j = 0; j < 4; j++) {
            unsigned v = 0;
            #pragma unroll
            for (int ww = 0; ww < 8; ww++) v |= colOrW[ww][j];
            if (v) {
                int lo = 4 * (__ffs(v) - 1) + j;  if (lo < xmin) xmin = lo;
                int hi = 4 * (31 - __clz(v)) + j; if (hi > xmax) xmax = hi;
            }
            unsigned r = rowBits[j];
            if (r) {
                int lo = __ffs(r) - 1 + 32 * j;  if (lo < ymin) ymin = lo;
                int hi = 31 - __clz(r) + 32 * j; if (hi > ymax) ymax = hi;
            }
        }
        float4 box;
        if (xmax >= 0) {
            float x0 = xmin * (1.f/128.f), x1 = (xmax + 1) * (1.f/128.f);
            float y0 = ymin * (1.f/128.f), y1 = (ymax + 1) * (1.f/128.f);
            box = make_float4((x0 + x1) * 0.5f, (y0 + y1) * 0.5f, x1 - x0, y1 - y0);
        } else {
            box = make_float4(0.f, 0.f, 0.f, 0.f);
        }
        ((float4*)g_box)[b] = box;
    }
}

// ---------------- fp32 tiled SGEMM (small out-projection only) --------------
template<int BM, int BN, int BK, int TM, int TN>
__global__ __launch_bounds__((BM/TM)*(BN/TN))
void sgemm_kernel(const float* __restrict__ A, const float* __restrict__ B,
                  const float* __restrict__ bias,
                  float* __restrict__ Cmat, int M, int N, int K) {
    constexpr int THREADS = (BM/TM)*(BN/TN);
    __shared__ float As[BK][BM];
    __shared__ float Bs[BK][BN];
    const int block_row = blockIdx.y * BM;
    const int block_col = blockIdx.x * BN;
    const int tid  = threadIdx.x;
    const int tcol = tid % (BN/TN);
    const int trow = tid / (BN/TN);

    float acc[TM][TN];
    #pragma unroll
    for (int i = 0; i < TM; i++)
        #pragma unroll
        for (int j = 0; j < TN; j++) acc[i][j] = 0.f;

    constexpr int AV = (BM*BK)/(4*THREADS);
    constexpr int BV = (BK*BN)/(4*THREADS);

    for (int k0 = 0; k0 < K; k0 += BK) {
        #pragma unroll
        for (int i = 0; i < AV; i++) {
            int v = tid + i * THREADS;
            int r  = v / (BK/4);
            int c4 = (v % (BK/4)) * 4;
            int rg = block_row + r; if (rg > M - 1) rg = M - 1;
            float4 a = *(const float4*)(A + (size_t)rg * K + k0 + c4);
            As[c4+0][r] = a.x; As[c4+1][r] = a.y; As[c4+2][r] = a.z; As[c4+3][r] = a.w;
        }
        #pragma unroll
        for (int i = 0; i < BV; i++) {
            int v = tid + i * THREADS;
            int r  = v / (BN/4);
            int c4 = (v % (BN/4)) * 4;
            *(float4*)(&Bs[r][c4]) = *(const float4*)(B + (size_t)(k0 + r) * N + block_col + c4);
        }
        __syncthreads();

        #pragma unroll
        for (int k = 0; k < BK; k++) {
            float ra[TM], rb[TN];
            #pragma unroll
            for (int i = 0; i < TM/2; i++) {
                ra[i]        = As[k][trow*(TM/2) + i];
                ra[i + TM/2] = As[k][BM/2 + trow*(TM/2) + i];
            }
            #pragma unroll
            for (int j = 0; j < TN/2; j++) {
                rb[j]        = Bs[k][tcol*(TN/2) + j];
                rb[j + TN/2] = Bs[k][BN/2 + tcol*(TN/2) + j];
            }
            #pragma unroll
            for (int i = 0; i < TM; i++)
                #pragma unroll
                for (int j = 0; j < TN; j++)
                    acc[i][j] += ra[i] * rb[j];
        }
        __syncthreads();
    }

    #pragma unroll
    for (int i = 0; i < TM; i++) {
        int rr = (i < TM/2) ? trow*(TM/2) + i : BM/2 + trow*(TM/2) + (i - TM/2);
        int r = block_row + rr;
        if (r >= M) continue;
        #pragma unroll
        for (int j = 0; j < TN; j++) {
            int cc = (j < TN/2) ? tcol*(TN/2) + j : BN/2 + tcol*(TN/2) + (j - TN/2);
            int c = block_col + cc;
            Cmat[(size_t)r * N + c] = acc[i][j] + bias[c];
        }
    }
}

// ---------------- kernel 4: sampling + softmax + bilinear gather -------------
__global__ __launch_bounds__(256) void sample_kernel() {
    int b = blockIdx.x;
    int n = b / LQ;
    int t = threadIdx.x, lane = t & 31, h = t >> 5;
    __shared__ int   s_idx[8][32][4];
    __shared__ float s_w[8][32][4];

    const int Wl_[4]    = {128, 64, 32, 16};
    const int start_[4] = {0, 16384, 20480, 21504};

    float4 box = ((const float4*)g_box)[b];

    int p = lane, l = p >> 3;
    float ox = g_off[(size_t)b * 512 + (h * 32 + p) * 2 + 0];
    float oy = g_off[(size_t)b * 512 + (h * 32 + p) * 2 + 1];
    float locx = box.x + ox * (1.f / 16.f) * box.z;
    float locy = box.y + oy * (1.f / 16.f) * box.w;

    int px = (int)(locx * 128.f); px = min(max(px, 0), 127);
    int py = (int)(locy * 128.f); py = min(max(py, 0), 127);
    // layout: word = y*4 + (x&3), bit = x>>2
    unsigned wbits = g_bits[(size_t)b * 512 + py * 4 + (px & 3)];
    float pin = ((wbits >> (px >> 2)) & 1u) ? 1.f : 0.f;

    float logit = g_attn[(size_t)b * 256 + h * 32 + p] * pin;
    float mx = logit;
    #pragma unroll
    for (int o = 16; o; o >>= 1) mx = fmaxf(mx, __shfl_xor_sync(0xffffffffu, mx, o));
    float e = expf(logit - mx);
    float sm = e;
    #pragma unroll
    for (int o = 16; o; o >>= 1) sm += __shfl_xor_sync(0xffffffffu, sm, o);
    float aw = e / sm;

    int Wl = Wl_[l], Hl = Wl;
    float pxf = locx * (float)Wl - 0.5f;
    float pyf = locy * (float)Hl - 0.5f;
    float x0f = floorf(pxf), y0f = floorf(pyf);
    float wx = pxf - x0f, wy = pyf - y0f;
    int x0 = (int)x0f, y0 = (int)y0f;
    int base = n * LEN_IN + start_[l];

    #pragma unroll
    for (int k = 0; k < 4; k++) {
        int xi = x0 + (k & 1), yi = y0 + (k >> 1);
        float cw = ((k & 1) ? wx : 1.f - wx) * ((k >> 1) ? wy : 1.f - wy);
        bool valid = (xi >= 0) && (xi < Wl) && (yi >= 0) && (yi < Hl);
        int xc = min(max(xi, 0), Wl - 1);
        int yc = min(max(yi, 0), Hl - 1);
        s_idx[h][p][k] = base + yc * Wl + xc;
        s_w[h][p][k]   = valid ? cw * aw : 0.f;
    }
    __syncwarp();

    int d = lane;
    const __half* vcol = g_valh + h * 32 + d;
    float acc = 0.f;
    #pragma unroll 4
    for (int pp = 0; pp < 32; pp++) {
        #pragma unroll
        for (int k = 0; k < 4; k++) {
            float wgt = s_w[h][pp][k];
            if (wgt != 0.f)
                acc += wgt * __half2float(vcol[(size_t)s_idx[h][pp][k] * 256]);
        }
    }
    g_samp[(size_t)b * 256 + h * 32 + d] = acc;
}

// ---------------- launch --------------------------------------------------
extern "C" void kernel_launch(void* const* d_in, const int* in_sizes, int n_in,
                              void* d_out, int out_size) {
    const float* query = (const float*)d_in[0];
    const float* masks = (const float*)d_in[2];
    const float* flat  = (const float*)d_in[4];
    const unsigned char* pad = (const unsigned char*)d_in[7];
    const float* Woff  = (const float*)d_in[8];
    const float* boff  = (const float*)d_in[9];
    const float* Wattn = (const float*)d_in[10];
    const float* battn = (const float*)d_in[11];
    const float* Wval  = (const float*)d_in[12];
    const float* bval  = (const float*)d_in[13];
    const float* Wout  = (const float*)d_in[14];
    const float* bout  = (const float*)d_in[15];
    float* out = (float*)d_out;

    float* sampp = nullptr;
    cudaGetSymbolAddress((void**)&sampp, g_samp);

    cudaFuncSetAttribute(value_gemm, cudaFuncAttributeMaxDynamicSharedMemorySize, VG_SMEM);

    // 1) masks -> packed bits + bboxes
    mask_kernel<<<NQ, 256>>>(masks);

    // 2) weight prep
    prep_Bval<<<32, 256>>>(Wval);
    prep_Bproj<<<192, 256>>>(Woff, Wattn);

    // 3) value = input_flatten @ W_val + b_val (fp16 HMMA, fp16 out)
    value_gemm<<<MROWS/64, 256, VG_SMEM>>>(flat, pad, bval);

    // 4) [offsets | logits] = query @ [Woff | Wattn] + bias (3-term fp16 HMMA)
    proj_gemm<<<dim3((NQ + 127)/128, 6), 256>>>(query, boff, battn);

    // 5) softmax + bilinear sampling
    sample_kernel<<<NQ, 256>>>();

    // 6) out = sampled @ W_out + b_out
    sgemm_kernel<64,64,16,4,4><<<dim3(CDIM/64, (NQ + 63)/64), 256>>>(
        sampp, Wout, bout, out, NQ, CDIM, CDIM);
}